// round 4
// baseline (speedup 1.0000x reference)
#include <cuda_runtime.h>
#include <cstdint>

#define B_    2048
#define N_    32
#define F_    64
#define E_    8
#define H_    128
#define NA_   4
#define NACT_ 16
#define K_TOT 585   // 512 (We@Wrel) + 64 (We@Wroot) + 8 (mask: be@Wrel) + 1 (bias)
#define K_MAIN 576  // rows handled by the uniform GEMM loop (9 tiles of 64)

// Folded weight matrix [K_TOT x H] — scratch (no allocations allowed)
__device__ float g_Wcat[K_TOT * H_];

// ---------------------------------------------------------------------------
// Kernel A: fold We/be into Wrel/Wroot/brel.  grid=585, block=128. ~19 MF.
// ---------------------------------------------------------------------------
__global__ void precompute_wcat(const float* __restrict__ We,
                                const float* __restrict__ be,
                                const float* __restrict__ Wrel,
                                const float* __restrict__ Wroot,
                                const float* __restrict__ brel) {
    __shared__ float vec[H_];
    const int r = blockIdx.x;
    const int h = threadIdx.x;
    const float* Bmat;
    float addv = 0.0f;
    if (r < 512) {                     // (We @ Wrel[e])[d,:]
        int e = r >> 6, d = r & 63;
        vec[h] = We[d * H_ + h];
        Bmat = Wrel + e * H_ * H_;
    } else if (r < 576) {              // (We @ Wroot)[d,:]
        int d = r - 512;
        vec[h] = We[d * H_ + h];
        Bmat = Wroot;
    } else if (r < 584) {              // be @ Wrel[e]
        int e = r - 576;
        vec[h] = be[h];
        Bmat = Wrel + e * H_ * H_;
    } else {                           // brel + be @ Wroot
        vec[h] = be[h];
        Bmat = Wroot;
        addv = brel[h];
    }
    __syncthreads();
    float acc = addv;
    #pragma unroll 8
    for (int t = 0; t < H_; ++t)
        acc = fmaf(vec[t], __ldg(Bmat + t * H_ + h), acc);
    g_Wcat[r * H_ + h] = acc;
}

// ---------------------------------------------------------------------------
// Kernel B: fully fused main kernel. One block per batch element.
// ---------------------------------------------------------------------------
struct SmemB {
    float ubarT[K_MAIN][N_];        // 73728 B: activation rows (agg + root), [k][j]
    union Ov {
        struct {
            float u[N_][F_];        // unary[b], UNPADDED (16B-aligned float4 rows)
            float cinv[E_ * N_];
        } p1;
        float wtile[64][H_];        // staged Wcat k-tile (GEMM phase)
    } ov;
    unsigned m[E_ * N_];            // bitmasks: m[e*32+j] bit i = A[b,e,i,j]
    float    pooled[H_];
    float    zs[NA_][H_];
    int      cols[NA_];
};

__global__ __launch_bounds__(256, 2) void critic_main(
    const float* __restrict__ unary,    // [B,N,F]
    const int*   __restrict__ binary,   // [B,N,N,E]
    const float* __restrict__ actions,  // [NA,B,NACT]
    const float* __restrict__ W1,       // [NA,H,H]
    const float* __restrict__ b1,       // [NA,H]
    const float* __restrict__ W2,       // [NA,H,NACT]
    const float* __restrict__ b2,       // [NA,NACT]
    float* __restrict__ qout)           // [NA,B,1]
{
    extern __shared__ char smem_raw[];
    SmemB& s = *reinterpret_cast<SmemB*>(smem_raw);

    const int tid  = threadIdx.x;
    const int b    = blockIdx.x;
    const int lane = tid & 31;
    const int w    = tid >> 5;

    // ---- load u[b] (2048 floats, coalesced) ----
    const float* ub = unary + (size_t)b * (N_ * F_);
    #pragma unroll
    for (int p = 0; p < 8; ++p) {
        int li = tid + p * 256;
        s.ov.p1.u[li >> 6][li & 63] = ub[li];
    }
    s.m[tid] = 0u;
    __syncthreads();

    // ---- binary[b] (8192 ints, int4-coalesced) -> bitmasks ----
    const int4* bb = reinterpret_cast<const int4*>(binary + (size_t)b * (N_ * N_ * E_));
    #pragma unroll
    for (int p = 0; p < 8; ++p) {
        int q4 = tid + p * 256;
        int4 v = bb[q4];
        int l  = q4 * 4;              // linear index (i*32 + j)*8 + e
        int i  = l >> 8;
        int j  = (l >> 3) & 31;
        int e0 = l & 7;               // 0 or 4
        unsigned bit = 1u << i;
        if (v.x) atomicOr(&s.m[(e0 + 0) * 32 + j], bit);
        if (v.y) atomicOr(&s.m[(e0 + 1) * 32 + j], bit);
        if (v.z) atomicOr(&s.m[(e0 + 2) * 32 + j], bit);
        if (v.w) atomicOr(&s.m[(e0 + 3) * 32 + j], bit);
    }
    __syncthreads();
    {
        int d = __popc(s.m[tid]);
        s.ov.p1.cinv[tid] = d ? (1.0f / (float)d) : 0.0f;
    }
    __syncthreads();

    // ========================================================================
    // Aggregation: thread = (d-group = warp, node j = lane).
    // Read u[i][8 floats] ONCE per i (broadcast LDS.128), apply to all 8
    // relations via bitmask-predicated adds. Lane j captures the broadcast at
    // i == lane to get its root-term row for free (no column reads of u).
    // Writes ubarT rows 0..511 (aggregated) and 512..575 (root).
    // ========================================================================
    {
        const int d0 = w * 8;   // this warp's 8 d-values
        unsigned mk[E_];
        float    ci[E_];
        #pragma unroll
        for (int e = 0; e < E_; ++e) {
            mk[e] = s.m[e * 32 + lane];
            ci[e] = s.ov.p1.cinv[e * 32 + lane];
        }
        float a8[E_][8];
        #pragma unroll
        for (int e = 0; e < E_; ++e)
            #pragma unroll
            for (int d = 0; d < 8; ++d) a8[e][d] = 0.0f;
        float root8[8];

        #pragma unroll 4
        for (int i = 0; i < N_; ++i) {
            float4 ua  = *reinterpret_cast<const float4*>(&s.ov.p1.u[i][d0]);
            float4 ubv = *reinterpret_cast<const float4*>(&s.ov.p1.u[i][d0 + 4]);
            if (i == lane) {   // capture own row for root term
                root8[0] = ua.x;  root8[1] = ua.y;
                root8[2] = ua.z;  root8[3] = ua.w;
                root8[4] = ubv.x; root8[5] = ubv.y;
                root8[6] = ubv.z; root8[7] = ubv.w;
            }
            #pragma unroll
            for (int e = 0; e < E_; ++e) {
                if ((mk[e] >> i) & 1u) {
                    a8[e][0] += ua.x;  a8[e][1] += ua.y;
                    a8[e][2] += ua.z;  a8[e][3] += ua.w;
                    a8[e][4] += ubv.x; a8[e][5] += ubv.y;
                    a8[e][6] += ubv.z; a8[e][7] += ubv.w;
                }
            }
        }
        #pragma unroll
        for (int e = 0; e < E_; ++e)
            #pragma unroll
            for (int d = 0; d < 8; ++d)
                s.ubarT[e * 64 + d0 + d][lane] = a8[e][d] * ci[e];

        // root fold: ubarT[512 + d0 + d][j] = u[j][d0 + d]
        #pragma unroll
        for (int d = 0; d < 8; ++d)
            s.ubarT[512 + d0 + d][lane] = root8[d];
    }
    __syncthreads();   // ubarT complete; u/cinv now dead (wtile reuses region)

    // ========================================================================
    // GEMM: h[j][c] = sum_k ubarT[k][j] * Wcat[k][c], k = 0..575.
    // Thread: 4 consecutive nodes x 4 consecutive cols (16 acc).
    //   nodes nj..nj+3 with nj = (lane&7)*4; cols cg*4 with cg = w*4 + (lane>>3).
    // Per k: 1 LDS.128 act + 1 LDS.128 wt + 16 FMA.
    // ========================================================================
    const int nj = (lane & 7) * 4;
    const int cg = w * 4 + (lane >> 3);

    float acc[4][4];
    #pragma unroll
    for (int n = 0; n < 4; ++n)
        #pragma unroll
        for (int c = 0; c < 4; ++c) acc[n][c] = 0.0f;

    for (int t = 0; t < 9; ++t) {
        // stage 64-row Wcat tile (coalesced float4)
        {
            const float4* src = reinterpret_cast<const float4*>(g_Wcat + (t * 64) * H_);
            float4*       dst = reinterpret_cast<float4*>(&s.ov.wtile[0][0]);
            #pragma unroll
            for (int p = 0; p < 8; ++p)
                dst[tid + p * 256] = src[tid + p * 256];
        }
        __syncthreads();
        #pragma unroll 8
        for (int k = 0; k < 64; ++k) {
            float4 av = *reinterpret_cast<const float4*>(&s.ubarT[t * 64 + k][nj]);
            float4 wv = *reinterpret_cast<const float4*>(&s.ov.wtile[k][cg * 4]);
            acc[0][0] = fmaf(av.x, wv.x, acc[0][0]);
            acc[0][1] = fmaf(av.x, wv.y, acc[0][1]);
            acc[0][2] = fmaf(av.x, wv.z, acc[0][2]);
            acc[0][3] = fmaf(av.x, wv.w, acc[0][3]);
            acc[1][0] = fmaf(av.y, wv.x, acc[1][0]);
            acc[1][1] = fmaf(av.y, wv.y, acc[1][1]);
            acc[1][2] = fmaf(av.y, wv.z, acc[1][2]);
            acc[1][3] = fmaf(av.y, wv.w, acc[1][3]);
            acc[2][0] = fmaf(av.z, wv.x, acc[2][0]);
            acc[2][1] = fmaf(av.z, wv.y, acc[2][1]);
            acc[2][2] = fmaf(av.z, wv.z, acc[2][2]);
            acc[2][3] = fmaf(av.z, wv.w, acc[2][3]);
            acc[3][0] = fmaf(av.w, wv.x, acc[3][0]);
            acc[3][1] = fmaf(av.w, wv.y, acc[3][1]);
            acc[3][2] = fmaf(av.w, wv.z, acc[3][2]);
            acc[3][3] = fmaf(av.w, wv.w, acc[3][3]);
        }
        __syncthreads();
    }

    // ---- mask-bias rows 576..583 + constant bias row 584 (direct L2) ----
    #pragma unroll
    for (int e = 0; e < E_; ++e) {
        float4 wv = __ldg(reinterpret_cast<const float4*>(
                          g_Wcat + (576 + e) * H_ + cg * 4));
        #pragma unroll
        for (int n = 0; n < 4; ++n) {
            if (s.m[e * 32 + nj + n]) {
                acc[n][0] += wv.x; acc[n][1] += wv.y;
                acc[n][2] += wv.z; acc[n][3] += wv.w;
            }
        }
    }
    {
        float4 wv = __ldg(reinterpret_cast<const float4*>(
                          g_Wcat + 584 * H_ + cg * 4));
        #pragma unroll
        for (int n = 0; n < 4; ++n) {
            acc[n][0] += wv.x; acc[n][1] += wv.y;
            acc[n][2] += wv.z; acc[n][3] += wv.w;
        }
    }

    // ---- relu + max-pool over nodes ----
    // per-thread max over its 4 nodes, then xor-shfl over the 8 node-groups
    // (lane bits 0..2), leaving pooled value replicated in each 8-lane group.
    #pragma unroll
    for (int c = 0; c < 4; ++c) {
        float v = fmaxf(fmaxf(fmaxf(acc[0][c], acc[1][c]),
                              fmaxf(acc[2][c], acc[3][c])), 0.0f);
        v = fmaxf(v, __shfl_xor_sync(0xffffffffu, v, 1));
        v = fmaxf(v, __shfl_xor_sync(0xffffffffu, v, 2));
        v = fmaxf(v, __shfl_xor_sync(0xffffffffu, v, 4));
        if ((lane & 7) == 0) s.pooled[cg * 4 + c] = v;
    }
    __syncthreads();

    // ---- per-agent heads: z = leaky(pooled@W1 + b1); q = z@W2[:,argmax] + b2 ----
    if (tid < NA_) {
        const float* ap = actions + ((size_t)tid * B_ + b) * NACT_;
        float best = ap[0]; int col = 0;
        #pragma unroll
        for (int k = 1; k < NACT_; ++k) {
            float v = ap[k];
            if (v > best) { best = v; col = k; }
        }
        s.cols[tid] = col;
    }
    {
        int a  = tid >> 6;       // agent
        int hh = tid & 63;
        #pragma unroll
        for (int rep = 0; rep < 2; ++rep) {
            int h = hh + rep * 64;
            float z = b1[a * H_ + h];
            const float* w1p = W1 + a * H_ * H_ + h;
            #pragma unroll 8
            for (int t = 0; t < H_; ++t)
                z = fmaf(s.pooled[t], __ldg(w1p + t * H_), z);
            z = (z > 0.0f) ? z : 0.01f * z;   // LeakyReLU
            s.zs[a][h] = z;
        }
    }
    __syncthreads();
    if (tid < NA_) {
        int a = tid;
        int col = s.cols[a];
        float q = b2[a * NACT_ + col];
        const float* w2p = W2 + a * H_ * NACT_ + col;
        #pragma unroll 8
        for (int h = 0; h < H_; ++h)
            q = fmaf(s.zs[a][h], __ldg(w2p + h * NACT_), q);
        qout[(size_t)a * B_ + b] = q;
    }
}

// ---------------------------------------------------------------------------
extern "C" void kernel_launch(void* const* d_in, const int* in_sizes, int n_in,
                              void* d_out, int out_size) {
    const float* unary   = (const float*)d_in[0];
    const int*   binary  = (const int*)  d_in[1];
    const float* actions = (const float*)d_in[2];
    const float* We      = (const float*)d_in[3];
    const float* be      = (const float*)d_in[4];
    const float* Wrel    = (const float*)d_in[5];
    const float* Wroot   = (const float*)d_in[6];
    const float* brel    = (const float*)d_in[7];
    const float* W1      = (const float*)d_in[8];
    const float* b1      = (const float*)d_in[9];
    const float* W2      = (const float*)d_in[10];
    const float* b2      = (const float*)d_in[11];
    float* qout = (float*)d_out;

    cudaFuncSetAttribute(critic_main, cudaFuncAttributeMaxDynamicSharedMemorySize,
                         (int)sizeof(SmemB));

    precompute_wcat<<<K_TOT, H_>>>(We, be, Wrel, Wroot, brel);
    critic_main<<<B_, 256, sizeof(SmemB)>>>(unary, binary, actions, W1, b1, W2, b2, qout);
}

// round 5
// speedup vs baseline: 1.6670x; 1.6670x over previous
#include <cuda_runtime.h>
#include <cstdint>

#define B_    2048
#define N_    32
#define F_    64
#define E_    8
#define H_    128
#define NA_   4
#define NACT_ 16
#define KTOT  585      // 512 agg + 64 root + 8 mask-bias + 1 const-bias
#define KK_   76       // k8 blocks (K padded to 608)
#define KPAD  608
#define ASTR  72       // A smem row stride in floats; 72%32==8 -> conflict-free frags
#define NCHUNK 19      // 19 chunks x 4 k8-blocks

// __device__ scratch (no allocations allowed)
__device__ float g_Wcat[KTOT * H_];            // logical [k][h]
__device__ uint4 g_Bpack[KK_ * 4 * 2 * 32];    // [kk][ng][half][t] fragment-packed tf32

static __device__ __forceinline__ uint32_t f2tf32(float f) {
    uint32_t r; asm("cvt.rna.tf32.f32 %0, %1;" : "=r"(r) : "f"(f)); return r;
}
static __device__ __forceinline__ void cp16(void* dst, const void* src) {
    uint32_t d = (uint32_t)__cvta_generic_to_shared(dst);
    asm volatile("cp.async.cg.shared.global [%0], [%1], 16;" :: "r"(d), "l"(src));
}
static __device__ __forceinline__ void mma_tf32(float c[4], const uint32_t a[4],
                                                uint32_t b0, uint32_t b1) {
    asm volatile(
        "mma.sync.aligned.m16n8k8.row.col.f32.tf32.tf32.f32 "
        "{%0,%1,%2,%3},{%4,%5,%6,%7},{%8,%9},{%0,%1,%2,%3};"
        : "+f"(c[0]), "+f"(c[1]), "+f"(c[2]), "+f"(c[3])
        : "r"(a[0]), "r"(a[1]), "r"(a[2]), "r"(a[3]), "r"(b0), "r"(b1));
}

// ---------------------------------------------------------------------------
// Kernel A: fold We/be into Wrel/Wroot/brel -> g_Wcat[585][128]
// ---------------------------------------------------------------------------
__global__ void precompute_wcat(const float* __restrict__ We,
                                const float* __restrict__ be,
                                const float* __restrict__ Wrel,
                                const float* __restrict__ Wroot,
                                const float* __restrict__ brel) {
    __shared__ float vec[H_];
    const int r = blockIdx.x;
    const int h = threadIdx.x;
    const float* Bmat;
    float addv = 0.0f;
    if (r < 512) {                     // (We @ Wrel[e])[d,:]
        int e = r >> 6, d = r & 63;
        vec[h] = We[d * H_ + h];
        Bmat = Wrel + e * H_ * H_;
    } else if (r < 576) {              // (We @ Wroot)[d,:]
        int d = r - 512;
        vec[h] = We[d * H_ + h];
        Bmat = Wroot;
    } else if (r < 584) {              // be @ Wrel[e]
        int e = r - 576;
        vec[h] = be[h];
        Bmat = Wrel + e * H_ * H_;
    } else {                           // brel + be @ Wroot
        vec[h] = be[h];
        Bmat = Wroot;
        addv = brel[h];
    }
    __syncthreads();
    float acc = addv;
    #pragma unroll 8
    for (int t = 0; t < H_; ++t)
        acc = fmaf(vec[t], __ldg(Bmat + t * H_ + h), acc);
    g_Wcat[r * H_ + h] = acc;
}

// ---------------------------------------------------------------------------
// Kernel A2: repack g_Wcat into mma B-fragment order (tf32), zero-pad k>=585.
// m16n8k8 col-major B frag: b0 = B[k=t%4][n=t/4], b1 = B[k=t%4+4][n=t/4].
// uint4 = {b0(nt0),b1(nt0),b0(nt1),b1(nt1)} with nt = half*2 + {0,1} within ng.
// ---------------------------------------------------------------------------
__global__ void repack_b() {
    int kk   = blockIdx.x;
    int t    = threadIdx.x & 31;
    int half = (threadIdx.x >> 5) & 1;
    int ng   = threadIdx.x >> 6;
    int k0 = kk * 8 + (t & 3);
    int k1 = k0 + 4;
    int c0 = ng * 32 + (half * 2 + 0) * 8 + (t >> 2);
    int c1 = ng * 32 + (half * 2 + 1) * 8 + (t >> 2);
    float v0 = (k0 < KTOT) ? g_Wcat[k0 * H_ + c0] : 0.f;
    float v1 = (k1 < KTOT) ? g_Wcat[k1 * H_ + c0] : 0.f;
    float v2 = (k0 < KTOT) ? g_Wcat[k0 * H_ + c1] : 0.f;
    float v3 = (k1 < KTOT) ? g_Wcat[k1 * H_ + c1] : 0.f;
    g_Bpack[((kk * 4 + ng) * 2 + half) * 32 + t] =
        make_uint4(f2tf32(v0), f2tf32(v1), f2tf32(v2), f2tf32(v3));
}

// ---------------------------------------------------------------------------
// Kernel B: main fused kernel. One block per 2 batch elements, 512 threads.
// ---------------------------------------------------------------------------
struct SmemM {
    float    A[KPAD][ASTR];          // 175104 B, k-major: A[k][m], m = q*32+j
    uint4    Bbuf[2][4][4][2][32];   // 32768 B: [buf][kkl][ng][half][t]
    unsigned masks[512];             // [q*256 + e*32 + j], bit i = A[b,e,i,j]
    float    cinv[512];
    float    pooled2[4][H_];         // per-m16-tile maxima
    float    pooled[2][H_];
    float    zs[2][NA_][H_];
    int      cols[8];
};

__global__ __launch_bounds__(512, 1) void critic_main(
    const float* __restrict__ unary,    // [B,N,F]
    const int*   __restrict__ binary,   // [B,N,N,E]
    const float* __restrict__ actions,  // [NA,B,NACT]
    const float* __restrict__ W1,       // [NA,H,H]
    const float* __restrict__ b1,       // [NA,H]
    const float* __restrict__ W2,       // [NA,H,NACT]
    const float* __restrict__ b2,       // [NA,NACT]
    float* __restrict__ qout)           // [NA,B,1]
{
    extern __shared__ char raw[];
    SmemM& s = *reinterpret_cast<SmemM*>(raw);

    const int tid  = threadIdx.x;
    const int lane = tid & 31;
    const int w    = tid >> 5;          // 16 warps
    const int bg0  = blockIdx.x * 2;    // first batch of this CTA

    // ---- u -> A root rows: A[512+d][q*32+j] = u[bg0+q][j][d] ----
    {
        const float* up = unary + (size_t)bg0 * (N_ * F_);
        #pragma unroll
        for (int p = 0; p < 8; ++p) {
            int li = tid + p * 512;            // 4096 elements
            int q  = li >> 11;
            int j  = (li >> 6) & 31;
            int d  = li & 63;
            s.A[512 + d][q * 32 + j] = up[li];
        }
    }
    s.masks[tid] = 0u;   // 512 entries, one per thread
    __syncthreads();

    // ---- binary -> bitmasks (2 batches, 4096 int4) ----
    {
        const int4* bb = reinterpret_cast<const int4*>(binary + (size_t)bg0 * (N_ * N_ * E_));
        #pragma unroll
        for (int p = 0; p < 8; ++p) {
            int q4 = tid + p * 512;
            int4 v = bb[q4];
            int l  = q4 * 4;               // q*8192 + (i*32+j)*8 + e
            int q  = l >> 13;
            int lb = l & 8191;
            int i  = lb >> 8;
            int j  = (lb >> 3) & 31;
            int e0 = lb & 7;               // 0 or 4
            unsigned bit = 1u << i;
            unsigned* mq = &s.masks[q * 256];
            if (v.x) atomicOr(&mq[(e0 + 0) * 32 + j], bit);
            if (v.y) atomicOr(&mq[(e0 + 1) * 32 + j], bit);
            if (v.z) atomicOr(&mq[(e0 + 2) * 32 + j], bit);
            if (v.w) atomicOr(&mq[(e0 + 3) * 32 + j], bit);
        }
    }

    // ---- prefetch B chunks 0 and 1 (independent of smem A work) ----
    {
        const uint4* src = g_Bpack;
        uint4* dst0 = &s.Bbuf[0][0][0][0][0];
        uint4* dst1 = &s.Bbuf[1][0][0][0][0];
        cp16(dst0 + tid, src + tid);
        cp16(dst0 + tid + 512, src + tid + 512);
        asm volatile("cp.async.commit_group;" ::: "memory");
        cp16(dst1 + tid, src + 1024 + tid);
        cp16(dst1 + tid + 512, src + 1024 + tid + 512);
        asm volatile("cp.async.commit_group;" ::: "memory");
    }
    __syncthreads();

    { int d = __popc(s.masks[tid]); s.cinv[tid] = d ? (1.0f / (float)d) : 0.0f; }
    __syncthreads();

    // ========================================================================
    // Aggregation into A rows. warp = (q = w>>3, dg = w&7), lane = node j.
    // Reads root rows as broadcasts; predicated adds across all 8 relations.
    // ========================================================================
    {
        const int q  = w >> 3;
        const int d0 = (w & 7) * 8;
        unsigned mk[E_];
        float    ci[E_];
        #pragma unroll
        for (int e = 0; e < E_; ++e) {
            mk[e] = s.masks[q * 256 + e * 32 + lane];
            ci[e] = s.cinv[q * 256 + e * 32 + lane];
        }
        float a8[E_][8];
        #pragma unroll
        for (int e = 0; e < E_; ++e)
            #pragma unroll
            for (int d = 0; d < 8; ++d) a8[e][d] = 0.0f;

        #pragma unroll 4
        for (int i = 0; i < N_; ++i) {
            float ud[8];
            #pragma unroll
            for (int dd = 0; dd < 8; ++dd)
                ud[dd] = s.A[512 + d0 + dd][q * 32 + i];   // broadcast
            #pragma unroll
            for (int e = 0; e < E_; ++e) {
                if ((mk[e] >> i) & 1u) {
                    #pragma unroll
                    for (int dd = 0; dd < 8; ++dd) a8[e][dd] += ud[dd];
                }
            }
        }
        #pragma unroll
        for (int e = 0; e < E_; ++e)
            #pragma unroll
            for (int dd = 0; dd < 8; ++dd)
                s.A[e * 64 + d0 + dd][q * 32 + lane] = a8[e][dd] * ci[e];

        // special k-rows: 576..583 deg>0 indicator, 584 ones, 585..607 zeros
        const int dg = w & 7;
        if (dg == 0) {
            #pragma unroll
            for (int e = 0; e < E_; ++e)
                s.A[576 + e][q * 32 + lane] = mk[e] ? 1.0f : 0.0f;
        } else if (dg == 1) {
            s.A[584][q * 32 + lane] = 1.0f;
        } else if (dg == 2) {
            #pragma unroll
            for (int rr = 0; rr < 23; ++rr)
                s.A[585 + rr][q * 32 + lane] = 0.0f;
        }
    }
    __syncthreads();   // A fully ready

    // ========================================================================
    // GEMM: C[m][n] = sum_k A[k][m] * Wcat[k][n], tf32 tensor cores.
    // warp: mw = w&3 (m16 tile), ng = w>>2 (n32 group). 4 n8 tiles per warp.
    // ========================================================================
    const int mw = w & 3;
    const int ng = w >> 2;
    const int fc = lane & 3;        // frag k-col
    const int fr = lane >> 2;       // frag row
    const int m0 = mw * 16;

    float acc[4][4];
    #pragma unroll
    for (int nt = 0; nt < 4; ++nt)
        #pragma unroll
        for (int i = 0; i < 4; ++i) acc[nt][i] = 0.0f;

    for (int ch = 0; ch < NCHUNK; ++ch) {
        asm volatile("cp.async.wait_group 1;" ::: "memory");
        __syncthreads();
        #pragma unroll
        for (int kkl = 0; kkl < 4; ++kkl) {
            const int k0 = (ch * 4 + kkl) * 8;
            uint32_t a[4];
            a[0] = f2tf32(s.A[k0 + fc][m0 + fr]);
            a[1] = f2tf32(s.A[k0 + fc][m0 + fr + 8]);
            a[2] = f2tf32(s.A[k0 + fc + 4][m0 + fr]);
            a[3] = f2tf32(s.A[k0 + fc + 4][m0 + fr + 8]);
            uint4 lo = s.Bbuf[ch & 1][kkl][ng][0][lane];
            uint4 hi = s.Bbuf[ch & 1][kkl][ng][1][lane];
            mma_tf32(acc[0], a, lo.x, lo.y);
            mma_tf32(acc[1], a, lo.z, lo.w);
            mma_tf32(acc[2], a, hi.x, hi.y);
            mma_tf32(acc[3], a, hi.z, hi.w);
        }
        __syncthreads();
        if (ch + 2 < NCHUNK) {
            const uint4* src = g_Bpack + (size_t)(ch + 2) * 1024;
            uint4* dst = &s.Bbuf[ch & 1][0][0][0][0];
            cp16(dst + tid, src + tid);
            cp16(dst + tid + 512, src + tid + 512);
            asm volatile("cp.async.commit_group;" ::: "memory");
        }
    }

    // ---- relu + max-pool over nodes ----
    // thread holds rows (fr, fr+8) of tile mw; cols 2*fc, 2*fc+1 per n8.
    #pragma unroll
    for (int nt = 0; nt < 4; ++nt) {
        float v0 = fmaxf(fmaxf(acc[nt][0], acc[nt][2]), 0.0f);
        float v1 = fmaxf(fmaxf(acc[nt][1], acc[nt][3]), 0.0f);
        #pragma unroll
        for (int off = 4; off < 32; off <<= 1) {
            v0 = fmaxf(v0, __shfl_xor_sync(0xffffffffu, v0, off));
            v1 = fmaxf(v1, __shfl_xor_sync(0xffffffffu, v1, off));
        }
        if (lane < 4) {
            int cb = ng * 32 + nt * 8 + 2 * lane;
            s.pooled2[mw][cb]     = v0;
            s.pooled2[mw][cb + 1] = v1;
        }
    }
    __syncthreads();
    if (tid < 256) {
        int q = tid >> 7, h = tid & 127;
        s.pooled[q][h] = fmaxf(s.pooled2[2 * q][h], s.pooled2[2 * q + 1][h]);
    }
    if (tid < 8) {   // argmax actions
        int q = tid >> 2, a = tid & 3;
        const float* ap = actions + ((size_t)a * B_ + bg0 + q) * NACT_;
        float best = ap[0]; int col = 0;
        #pragma unroll
        for (int k = 1; k < NACT_; ++k) {
            float v = ap[k];
            if (v > best) { best = v; col = k; }
        }
        s.cols[tid] = col;
    }
    __syncthreads();

    // ---- heads: z = leaky(pooled@W1 + b1), both batches share each W1 load ----
    {
        int a = tid >> 7, h = tid & 127;
        float z0 = b1[a * H_ + h], z1 = z0;
        const float* w1p = W1 + a * H_ * H_ + h;
        #pragma unroll 4
        for (int t = 0; t < H_; ++t) {
            float wv = __ldg(w1p + t * H_);
            z0 = fmaf(s.pooled[0][t], wv, z0);
            z1 = fmaf(s.pooled[1][t], wv, z1);
        }
        s.zs[0][a][h] = (z0 > 0.0f) ? z0 : 0.01f * z0;
        s.zs[1][a][h] = (z1 > 0.0f) ? z1 : 0.01f * z1;
    }
    __syncthreads();
    if (tid < 8) {
        int q = tid >> 2, a = tid & 3, col = s.cols[tid];
        float qv = b2[a * NACT_ + col];
        const float* w2p = W2 + a * H_ * NACT_ + col;
        #pragma unroll 8
        for (int h = 0; h < H_; ++h)
            qv = fmaf(s.zs[q][a][h], __ldg(w2p + h * NACT_), qv);
        qout[(size_t)a * B_ + bg0 + q] = qv;
    }
}

// ---------------------------------------------------------------------------
extern "C" void kernel_launch(void* const* d_in, const int* in_sizes, int n_in,
                              void* d_out, int out_size) {
    const float* unary   = (const float*)d_in[0];
    const int*   binary  = (const int*)  d_in[1];
    const float* actions = (const float*)d_in[2];
    const float* We      = (const float*)d_in[3];
    const float* be      = (const float*)d_in[4];
    const float* Wrel    = (const float*)d_in[5];
    const float* Wroot   = (const float*)d_in[6];
    const float* brel    = (const float*)d_in[7];
    const float* W1      = (const float*)d_in[8];
    const float* b1      = (const float*)d_in[9];
    const float* W2      = (const float*)d_in[10];
    const float* b2      = (const float*)d_in[11];
    float* qout = (float*)d_out;

    cudaFuncSetAttribute(critic_main, cudaFuncAttributeMaxDynamicSharedMemorySize,
                         (int)sizeof(SmemM));

    precompute_wcat<<<KTOT, H_>>>(We, be, Wrel, Wroot, brel);
    repack_b<<<KK_, 256>>>();
    critic_main<<<B_ / 2, 512, sizeof(SmemM)>>>(unary, binary, actions,
                                                W1, b1, W2, b2, qout);
}

// round 6
// speedup vs baseline: 2.6880x; 1.6124x over previous
#include <cuda_runtime.h>
#include <cstdint>

#define B_    2048
#define N_    32
#define F_    64
#define E_    8
#define H_    128
#define NA_   4
#define NACT_ 16
#define KTOT  585      // 512 agg + 64 root + 8 mask-bias + 1 const-bias
#define KK_   76       // k8 blocks (K padded to 608)
#define KPAD  608
#define ASTR  72       // A smem row stride in floats; 72%32==8 -> conflict-free frags
#define NCHUNK 19      // 19 chunks x 4 k8-blocks

// __device__ scratch (no allocations allowed)
__device__ float g_Wcat[KTOT * H_];            // logical [k][h]
__device__ uint4 g_Bpack[KK_ * 4 * 2 * 32];    // [kk][ng][half][t] fragment-packed tf32
__device__ float g_pooled[B_ * H_];            // [b][h]

static __device__ __forceinline__ uint32_t f2tf32(float f) {
    uint32_t r; asm("cvt.rna.tf32.f32 %0, %1;" : "=r"(r) : "f"(f)); return r;
}
static __device__ __forceinline__ void cp16(void* dst, const void* src) {
    uint32_t d = (uint32_t)__cvta_generic_to_shared(dst);
    asm volatile("cp.async.cg.shared.global [%0], [%1], 16;" :: "r"(d), "l"(src));
}
static __device__ __forceinline__ void mma_tf32(float c[4], const uint32_t a[4],
                                                uint32_t b0, uint32_t b1) {
    asm volatile(
        "mma.sync.aligned.m16n8k8.row.col.f32.tf32.tf32.f32 "
        "{%0,%1,%2,%3},{%4,%5,%6,%7},{%8,%9},{%0,%1,%2,%3};"
        : "+f"(c[0]), "+f"(c[1]), "+f"(c[2]), "+f"(c[3])
        : "r"(a[0]), "r"(a[1]), "r"(a[2]), "r"(a[3]), "r"(b0), "r"(b1));
}
static __device__ __forceinline__ uint64_t pk2(float lo, float hi) {
    uint64_t r; asm("mov.b64 %0, {%1, %2};" : "=l"(r) : "f"(lo), "f"(hi)); return r;
}
static __device__ __forceinline__ void upk2(uint64_t v, float& lo, float& hi) {
    asm("mov.b64 {%0, %1}, %2;" : "=f"(lo), "=f"(hi) : "l"(v));
}
static __device__ __forceinline__ uint64_t fma2(uint64_t a, uint64_t b, uint64_t c) {
    uint64_t d; asm("fma.rn.f32x2 %0, %1, %2, %3;" : "=l"(d) : "l"(a), "l"(b), "l"(c));
    return d;
}

// ---------------------------------------------------------------------------
// Kernel A: fold We/be into Wrel/Wroot/brel -> g_Wcat[585][128]
// ---------------------------------------------------------------------------
__global__ void precompute_wcat(const float* __restrict__ We,
                                const float* __restrict__ be,
                                const float* __restrict__ Wrel,
                                const float* __restrict__ Wroot,
                                const float* __restrict__ brel) {
    __shared__ float vec[H_];
    const int r = blockIdx.x;
    const int h = threadIdx.x;
    const float* Bmat;
    float addv = 0.0f;
    if (r < 512) {                     // (We @ Wrel[e])[d,:]
        int e = r >> 6, d = r & 63;
        vec[h] = We[d * H_ + h];
        Bmat = Wrel + e * H_ * H_;
    } else if (r < 576) {              // (We @ Wroot)[d,:]
        int d = r - 512;
        vec[h] = We[d * H_ + h];
        Bmat = Wroot;
    } else if (r < 584) {              // be @ Wrel[e]
        int e = r - 576;
        vec[h] = be[h];
        Bmat = Wrel + e * H_ * H_;
    } else {                           // brel + be @ Wroot
        vec[h] = be[h];
        Bmat = Wroot;
        addv = brel[h];
    }
    __syncthreads();
    float a0 = 0.f, a1 = 0.f, a2 = 0.f, a3 = 0.f;
    #pragma unroll 8
    for (int t = 0; t < H_; t += 4) {
        a0 = fmaf(vec[t],     __ldg(Bmat + (t    ) * H_ + h), a0);
        a1 = fmaf(vec[t + 1], __ldg(Bmat + (t + 1) * H_ + h), a1);
        a2 = fmaf(vec[t + 2], __ldg(Bmat + (t + 2) * H_ + h), a2);
        a3 = fmaf(vec[t + 3], __ldg(Bmat + (t + 3) * H_ + h), a3);
    }
    g_Wcat[r * H_ + h] = addv + ((a0 + a1) + (a2 + a3));
}

// ---------------------------------------------------------------------------
// Kernel A2: repack g_Wcat into mma B-fragment order (tf32), zero-pad k>=585.
// ---------------------------------------------------------------------------
__global__ void repack_b() {
    int kk   = blockIdx.x;
    int t    = threadIdx.x & 31;
    int half = (threadIdx.x >> 5) & 1;
    int ng   = threadIdx.x >> 6;
    int k0 = kk * 8 + (t & 3);
    int k1 = k0 + 4;
    int c0 = ng * 32 + (half * 2 + 0) * 8 + (t >> 2);
    int c1 = ng * 32 + (half * 2 + 1) * 8 + (t >> 2);
    float v0 = (k0 < KTOT) ? g_Wcat[k0 * H_ + c0] : 0.f;
    float v1 = (k1 < KTOT) ? g_Wcat[k1 * H_ + c0] : 0.f;
    float v2 = (k0 < KTOT) ? g_Wcat[k0 * H_ + c1] : 0.f;
    float v3 = (k1 < KTOT) ? g_Wcat[k1 * H_ + c1] : 0.f;
    g_Bpack[((kk * 4 + ng) * 2 + half) * 32 + t] =
        make_uint4(f2tf32(v0), f2tf32(v1), f2tf32(v2), f2tf32(v3));
}

// ---------------------------------------------------------------------------
// Kernel B: main kernel. One block per 2 batch elements, 512 threads.
// Ends at max-pool; writes g_pooled.
// ---------------------------------------------------------------------------
struct SmemM {
    float    A[KPAD][ASTR];          // 175104 B, k-major: A[k][m], m = q*32+j
    uint4    Bbuf[2][4][4][2][32];   // 32768 B: [buf][kkl][ng][half][t]
    unsigned masks[512];             // [q*256 + e*32 + j], bit i = A[b,e,i,j]
    float    cinv[512];
    float    pooled2[4][H_];         // per-m16-tile maxima
};

__global__ __launch_bounds__(512, 1) void critic_main(
    const float* __restrict__ unary,    // [B,N,F]
    const int*   __restrict__ binary)   // [B,N,N,E]
{
    extern __shared__ char raw[];
    SmemM& s = *reinterpret_cast<SmemM*>(raw);

    const int tid  = threadIdx.x;
    const int lane = tid & 31;
    const int w    = tid >> 5;          // 16 warps
    const int bg0  = blockIdx.x * 2;    // first batch of this CTA

    // ---- u -> A root rows: A[512+d][q*32+j] = u[bg0+q][j][d] ----
    {
        const float* up = unary + (size_t)bg0 * (N_ * F_);
        #pragma unroll
        for (int p = 0; p < 8; ++p) {
            int li = tid + p * 512;            // 4096 elements
            int q  = li >> 11;
            int j  = (li >> 6) & 31;
            int d  = li & 63;
            s.A[512 + d][q * 32 + j] = up[li];
        }
    }
    s.masks[tid] = 0u;
    __syncthreads();

    // ---- binary -> bitmasks (2 batches, 4096 int4) ----
    {
        const int4* bb = reinterpret_cast<const int4*>(binary + (size_t)bg0 * (N_ * N_ * E_));
        #pragma unroll
        for (int p = 0; p < 8; ++p) {
            int q4 = tid + p * 512;
            int4 v = bb[q4];
            int l  = q4 * 4;               // q*8192 + (i*32+j)*8 + e
            int q  = l >> 13;
            int lb = l & 8191;
            int i  = lb >> 8;
            int j  = (lb >> 3) & 31;
            int e0 = lb & 7;               // 0 or 4
            unsigned bit = 1u << i;
            unsigned* mq = &s.masks[q * 256];
            if (v.x) atomicOr(&mq[(e0 + 0) * 32 + j], bit);
            if (v.y) atomicOr(&mq[(e0 + 1) * 32 + j], bit);
            if (v.z) atomicOr(&mq[(e0 + 2) * 32 + j], bit);
            if (v.w) atomicOr(&mq[(e0 + 3) * 32 + j], bit);
        }
    }

    // ---- prefetch B chunks 0 and 1 ----
    {
        const uint4* src = g_Bpack;
        uint4* dst0 = &s.Bbuf[0][0][0][0][0];
        uint4* dst1 = &s.Bbuf[1][0][0][0][0];
        cp16(dst0 + tid, src + tid);
        cp16(dst0 + tid + 512, src + tid + 512);
        asm volatile("cp.async.commit_group;" ::: "memory");
        cp16(dst1 + tid, src + 1024 + tid);
        cp16(dst1 + tid + 512, src + 1024 + tid + 512);
        asm volatile("cp.async.commit_group;" ::: "memory");
    }
    __syncthreads();

    { int d = __popc(s.masks[tid]); s.cinv[tid] = d ? (1.0f / (float)d) : 0.0f; }
    __syncthreads();

    // ========================================================================
    // Tensor-core aggregation: S_e[j][d] = sum_i adj_e[i,j] * u[i,d].
    // mma m16n8k8: A-op = adjacency bits (exact {0,1} tf32 from masks regs),
    // B-op = u from A root rows. warp = (q = w>>3, mt = (w>>2)&1, np = w&3):
    // m16 tile mt (j range), n-tiles 2np,2np+1 (d range), all 8 e, all 4 k8.
    // C scaled by cinv and stored into A rows 0..511 (k = e*64 + d).
    // ========================================================================
    {
        const int gr = lane >> 2, gc = lane & 3;
        const int q  = w >> 3;
        const int mt = (w >> 2) & 1;
        const int np = w & 3;

        uint32_t uf[2][4][2];     // [nt2][kb][b0/b1]
        #pragma unroll
        for (int nt2 = 0; nt2 < 2; ++nt2) {
            int nt = np * 2 + nt2;
            #pragma unroll
            for (int kb = 0; kb < 4; ++kb) {
                uf[nt2][kb][0] = f2tf32(s.A[512 + nt * 8 + gr][q * 32 + kb * 8 + gc]);
                uf[nt2][kb][1] = f2tf32(s.A[512 + nt * 8 + gr][q * 32 + kb * 8 + gc + 4]);
            }
        }
        const int mcol = q * 32 + mt * 16 + gr;
        #pragma unroll
        for (int e = 0; e < E_; ++e) {
            const int mb = q * 256 + e * 32 + mt * 16 + gr;
            unsigned mr0 = s.masks[mb];
            unsigned mr1 = s.masks[mb + 8];
            float ci0 = s.cinv[mb];
            float ci1 = s.cinv[mb + 8];
            float acc0[4] = {0.f, 0.f, 0.f, 0.f};
            float acc1[4] = {0.f, 0.f, 0.f, 0.f};
            #pragma unroll
            for (int kb = 0; kb < 4; ++kb) {
                int bi = kb * 8 + gc;
                uint32_t ar[4];
                ar[0] = ((mr0 >> bi) & 1u)       ? 0x3f800000u : 0u;
                ar[1] = ((mr1 >> bi) & 1u)       ? 0x3f800000u : 0u;
                ar[2] = ((mr0 >> (bi + 4)) & 1u) ? 0x3f800000u : 0u;
                ar[3] = ((mr1 >> (bi + 4)) & 1u) ? 0x3f800000u : 0u;
                mma_tf32(acc0, ar, uf[0][kb][0], uf[0][kb][1]);
                mma_tf32(acc1, ar, uf[1][kb][0], uf[1][kb][1]);
            }
            {
                int row = e * 64 + (np * 2 + 0) * 8 + 2 * gc;
                s.A[row][mcol]         = acc0[0] * ci0;
                s.A[row + 1][mcol]     = acc0[1] * ci0;
                s.A[row][mcol + 8]     = acc0[2] * ci1;
                s.A[row + 1][mcol + 8] = acc0[3] * ci1;
            }
            {
                int row = e * 64 + (np * 2 + 1) * 8 + 2 * gc;
                s.A[row][mcol]         = acc1[0] * ci0;
                s.A[row + 1][mcol]     = acc1[1] * ci0;
                s.A[row][mcol + 8]     = acc1[2] * ci1;
                s.A[row + 1][mcol + 8] = acc1[3] * ci1;
            }
        }
    }
    // special k-rows: 576..583 deg>0 indicator, 584 ones, 585..607 zeros
    {
        int q2 = tid >> 8, e2 = (tid >> 5) & 7, j2 = tid & 31;
        s.A[576 + e2][q2 * 32 + j2] = s.masks[tid] ? 1.0f : 0.0f;
        if (tid < 64) s.A[584][tid] = 1.0f;
        for (int r = tid; r < 23 * 64; r += 512)
            s.A[585 + (r >> 6)][r & 63] = 0.0f;
    }
    __syncthreads();   // A fully ready

    // ========================================================================
    // Main GEMM: C[m][n] = sum_k A[k][m] * Wcat[k][n], tf32 tensor cores.
    // ========================================================================
    const int mw = w & 3;
    const int ng = w >> 2;
    const int fc = lane & 3;
    const int fr = lane >> 2;
    const int m0 = mw * 16;

    float acc[4][4];
    #pragma unroll
    for (int nt = 0; nt < 4; ++nt)
        #pragma unroll
        for (int i = 0; i < 4; ++i) acc[nt][i] = 0.0f;

    for (int ch = 0; ch < NCHUNK; ++ch) {
        asm volatile("cp.async.wait_group 1;" ::: "memory");
        __syncthreads();
        #pragma unroll
        for (int kkl = 0; kkl < 4; ++kkl) {
            const int k0 = (ch * 4 + kkl) * 8;
            uint32_t a[4];
            a[0] = f2tf32(s.A[k0 + fc][m0 + fr]);
            a[1] = f2tf32(s.A[k0 + fc][m0 + fr + 8]);
            a[2] = f2tf32(s.A[k0 + fc + 4][m0 + fr]);
            a[3] = f2tf32(s.A[k0 + fc + 4][m0 + fr + 8]);
            uint4 lo = s.Bbuf[ch & 1][kkl][ng][0][lane];
            uint4 hi = s.Bbuf[ch & 1][kkl][ng][1][lane];
            mma_tf32(acc[0], a, lo.x, lo.y);
            mma_tf32(acc[1], a, lo.z, lo.w);
            mma_tf32(acc[2], a, hi.x, hi.y);
            mma_tf32(acc[3], a, hi.z, hi.w);
        }
        __syncthreads();
        if (ch + 2 < NCHUNK) {
            const uint4* src = g_Bpack + (size_t)(ch + 2) * 1024;
            uint4* dst = &s.Bbuf[ch & 1][0][0][0][0];
            cp16(dst + tid, src + tid);
            cp16(dst + tid + 512, src + tid + 512);
            asm volatile("cp.async.commit_group;" ::: "memory");
        }
    }

    // ---- relu + max-pool over nodes ----
    #pragma unroll
    for (int nt = 0; nt < 4; ++nt) {
        float v0 = fmaxf(fmaxf(acc[nt][0], acc[nt][2]), 0.0f);
        float v1 = fmaxf(fmaxf(acc[nt][1], acc[nt][3]), 0.0f);
        #pragma unroll
        for (int off = 4; off < 32; off <<= 1) {
            v0 = fmaxf(v0, __shfl_xor_sync(0xffffffffu, v0, off));
            v1 = fmaxf(v1, __shfl_xor_sync(0xffffffffu, v1, off));
        }
        if (lane < 4) {
            int cb = ng * 32 + nt * 8 + 2 * lane;
            s.pooled2[mw][cb]     = v0;
            s.pooled2[mw][cb + 1] = v1;
        }
    }
    __syncthreads();
    if (tid < 256) {
        int q = tid >> 7, h = tid & 127;
        g_pooled[(size_t)(bg0 + q) * H_ + h] =
            fmaxf(s.pooled2[2 * q][h], s.pooled2[2 * q + 1][h]);
    }
}

// ---------------------------------------------------------------------------
// Kernel C: heads. grid = 4 agents x 32 batch-tiles of 64, block 256.
// W1 staged once per CTA; z via packed f32x2 FMA; q via argmax-gathered W2 col.
// ---------------------------------------------------------------------------
struct SmemH {
    float P[64][H_];      // pooled tile     32768 B
    float W[H_][H_];      // W1[a]           65536 B
    float Z[64][132];     // z (padded rows) 33792 B
    int   cols[64];
};

__global__ __launch_bounds__(256, 1) void heads_kernel(
    const float* __restrict__ actions,  // [NA,B,NACT]
    const float* __restrict__ W1,       // [NA,H,H]
    const float* __restrict__ b1,       // [NA,H]
    const float* __restrict__ W2,       // [NA,H,NACT]
    const float* __restrict__ b2,       // [NA,NACT]
    float* __restrict__ qout)           // [NA,B,1]
{
    extern __shared__ char raw[];
    SmemH& s = *reinterpret_cast<SmemH*>(raw);
    const int tid = threadIdx.x;
    const int a   = blockIdx.x >> 5;
    const int b0  = (blockIdx.x & 31) * 64;

    // stage pooled tile + W1[a]
    {
        const float4* ps = reinterpret_cast<const float4*>(g_pooled + (size_t)b0 * H_);
        float4* pd = reinterpret_cast<float4*>(&s.P[0][0]);
        #pragma unroll
        for (int p = 0; p < 8; ++p) pd[tid + p * 256] = ps[tid + p * 256];
        const float4* ws = reinterpret_cast<const float4*>(W1 + (size_t)a * H_ * H_);
        float4* wd = reinterpret_cast<float4*>(&s.W[0][0]);
        #pragma unroll
        for (int p = 0; p < 16; ++p) wd[tid + p * 256] = ws[tid + p * 256];
    }
    if (tid < 64) {
        const float* ap = actions + ((size_t)a * B_ + b0 + tid) * NACT_;
        float best = ap[0]; int col = 0;
        #pragma unroll
        for (int k = 1; k < NACT_; ++k) {
            float v = ap[k];
            if (v > best) { best = v; col = k; }
        }
        s.cols[tid] = col;
    }
    __syncthreads();

    // z = leaky(P @ W + b1): thread = (bi = tid>>5: 8 batches, hi = tid&31: 4 h)
    {
        const int bi = tid >> 5;
        const int hi = tid & 31;
        float4 bv = *reinterpret_cast<const float4*>(b1 + a * H_ + hi * 4);
        uint64_t zp[8][2];
        #pragma unroll
        for (int r = 0; r < 8; ++r) {
            zp[r][0] = pk2(bv.x, bv.y);
            zp[r][1] = pk2(bv.z, bv.w);
        }
        #pragma unroll 4
        for (int k = 0; k < H_; ++k) {
            float4 wv = *reinterpret_cast<const float4*>(&s.W[k][hi * 4]);
            uint64_t w01 = pk2(wv.x, wv.y);
            uint64_t w23 = pk2(wv.z, wv.w);
            #pragma unroll
            for (int r = 0; r < 8; ++r) {
                float pv = s.P[bi * 8 + r][k];     // warp-uniform broadcast
                uint64_t pv2 = pk2(pv, pv);
                zp[r][0] = fma2(pv2, w01, zp[r][0]);
                zp[r][1] = fma2(pv2, w23, zp[r][1]);
            }
        }
        #pragma unroll
        for (int r = 0; r < 8; ++r) {
            float z0, z1, z2, z3;
            upk2(zp[r][0], z0, z1);
            upk2(zp[r][1], z2, z3);
            z0 = (z0 > 0.f) ? z0 : 0.01f * z0;
            z1 = (z1 > 0.f) ? z1 : 0.01f * z1;
            z2 = (z2 > 0.f) ? z2 : 0.01f * z2;
            z3 = (z3 > 0.f) ? z3 : 0.01f * z3;
            float* zr = &s.Z[bi * 8 + r][hi * 4];
            zr[0] = z0; zr[1] = z1; zr[2] = z2; zr[3] = z3;
        }
    }
    __syncthreads();

    // q = z @ W2[:, col] + b2: thread = (b = tid>>2, qt = tid&3)
    {
        const int b  = tid >> 2;
        const int qt = tid & 3;
        const int col = s.cols[b];
        const float* w2p = W2 + (size_t)a * H_ * NACT_ + col;
        float part = 0.f;
        #pragma unroll 8
        for (int i = 0; i < 32; ++i) {
            int h = i * 4 + qt;                 // (4b+4i+qt)%32 distinct: no conflicts
            part = fmaf(s.Z[b][h], __ldg(w2p + h * NACT_), part);
        }
        part += __shfl_xor_sync(0xffffffffu, part, 1);
        part += __shfl_xor_sync(0xffffffffu, part, 2);
        if (qt == 0)
            qout[(size_t)a * B_ + b0 + b] = part + b2[a * NACT_ + col];
    }
}

// ---------------------------------------------------------------------------
extern "C" void kernel_launch(void* const* d_in, const int* in_sizes, int n_in,
                              void* d_out, int out_size) {
    const float* unary   = (const float*)d_in[0];
    const int*   binary  = (const int*)  d_in[1];
    const float* actions = (const float*)d_in[2];
    const float* We      = (const float*)d_in[3];
    const float* be      = (const float*)d_in[4];
    const float* Wrel    = (const float*)d_in[5];
    const float* Wroot   = (const float*)d_in[6];
    const float* brel    = (const float*)d_in[7];
    const float* W1      = (const float*)d_in[8];
    const float* b1      = (const float*)d_in[9];
    const float* W2      = (const float*)d_in[10];
    const float* b2      = (const float*)d_in[11];
    float* qout = (float*)d_out;

    cudaFuncSetAttribute(critic_main, cudaFuncAttributeMaxDynamicSharedMemorySize,
                         (int)sizeof(SmemM));
    cudaFuncSetAttribute(heads_kernel, cudaFuncAttributeMaxDynamicSharedMemorySize,
                         (int)sizeof(SmemH));

    precompute_wcat<<<KTOT, H_>>>(We, be, Wrel, Wroot, brel);
    repack_b<<<KK_, 256>>>();
    critic_main<<<B_ / 2, 512, sizeof(SmemM)>>>(unary, binary);
    heads_kernel<<<NA_ * 32, 256, sizeof(SmemH)>>>(actions, W1, b1, W2, b2, qout);
}

// round 7
// speedup vs baseline: 2.7022x; 1.0053x over previous
#include <cuda_runtime.h>
#include <cstdint>

#define B_    2048
#define N_    32
#define F_    64
#define E_    8
#define H_    128
#define NA_   4
#define NACT_ 16
#define KTOT  585      // 512 agg + 64 root + 8 mask-bias + 1 const-bias
#define KK_   76       // k8 blocks (K padded to 608)
#define KPAD  608
#define ASTR  72       // A smem row stride in floats; 72%32==8 -> conflict-free frags
#define NCHUNK 19      // 19 chunks x 4 k8-blocks

// __device__ scratch (no allocations allowed)
__device__ float g_Wcat[KTOT * H_];            // logical [k][h]
__device__ uint4 g_Bpack[KK_ * 4 * 2 * 32];    // [kk][ng][half][t] fragment-packed tf32
__device__ float g_pooled[B_ * H_];            // [b][h]

static __device__ __forceinline__ uint32_t f2tf32(float f) {
    uint32_t r; asm("cvt.rna.tf32.f32 %0, %1;" : "=r"(r) : "f"(f)); return r;
}
static __device__ __forceinline__ void cp16(void* dst, const void* src) {
    uint32_t d = (uint32_t)__cvta_generic_to_shared(dst);
    asm volatile("cp.async.cg.shared.global [%0], [%1], 16;" :: "r"(d), "l"(src));
}
static __device__ __forceinline__ void mma_tf32(float c[4], const uint32_t a[4],
                                                uint32_t b0, uint32_t b1) {
    asm volatile(
        "mma.sync.aligned.m16n8k8.row.col.f32.tf32.tf32.f32 "
        "{%0,%1,%2,%3},{%4,%5,%6,%7},{%8,%9},{%0,%1,%2,%3};"
        : "+f"(c[0]), "+f"(c[1]), "+f"(c[2]), "+f"(c[3])
        : "r"(a[0]), "r"(a[1]), "r"(a[2]), "r"(a[3]), "r"(b0), "r"(b1));
}
static __device__ __forceinline__ uint64_t pk2(float lo, float hi) {
    uint64_t r; asm("mov.b64 %0, {%1, %2};" : "=l"(r) : "f"(lo), "f"(hi)); return r;
}
static __device__ __forceinline__ void upk2(uint64_t v, float& lo, float& hi) {
    asm("mov.b64 {%0, %1}, %2;" : "=f"(lo), "=f"(hi) : "l"(v));
}
static __device__ __forceinline__ uint64_t fma2(uint64_t a, uint64_t b, uint64_t c) {
    uint64_t d; asm("fma.rn.f32x2 %0, %1, %2, %3;" : "=l"(d) : "l"(a), "l"(b), "l"(c));
    return d;
}

// ---------------------------------------------------------------------------
// Kernel A: fold We/be into Wrel/Wroot/brel -> g_Wcat[585][128]
// ---------------------------------------------------------------------------
__global__ void precompute_wcat(const float* __restrict__ We,
                                const float* __restrict__ be,
                                const float* __restrict__ Wrel,
                                const float* __restrict__ Wroot,
                                const float* __restrict__ brel) {
    __shared__ float vec[H_];
    const int r = blockIdx.x;
    const int h = threadIdx.x;
    const float* Bmat;
    float addv = 0.0f;
    if (r < 512) {                     // (We @ Wrel[e])[d,:]
        int e = r >> 6, d = r & 63;
        vec[h] = We[d * H_ + h];
        Bmat = Wrel + e * H_ * H_;
    } else if (r < 576) {              // (We @ Wroot)[d,:]
        int d = r - 512;
        vec[h] = We[d * H_ + h];
        Bmat = Wroot;
    } else if (r < 584) {              // be @ Wrel[e]
        int e = r - 576;
        vec[h] = be[h];
        Bmat = Wrel + e * H_ * H_;
    } else {                           // brel + be @ Wroot
        vec[h] = be[h];
        Bmat = Wroot;
        addv = brel[h];
    }
    __syncthreads();
    float a0 = 0.f, a1 = 0.f, a2 = 0.f, a3 = 0.f;
    #pragma unroll 8
    for (int t = 0; t < H_; t += 4) {
        a0 = fmaf(vec[t],     __ldg(Bmat + (t    ) * H_ + h), a0);
        a1 = fmaf(vec[t + 1], __ldg(Bmat + (t + 1) * H_ + h), a1);
        a2 = fmaf(vec[t + 2], __ldg(Bmat + (t + 2) * H_ + h), a2);
        a3 = fmaf(vec[t + 3], __ldg(Bmat + (t + 3) * H_ + h), a3);
    }
    g_Wcat[r * H_ + h] = addv + ((a0 + a1) + (a2 + a3));
}

// ---------------------------------------------------------------------------
// Kernel A2: repack g_Wcat into mma B-fragment order (tf32), zero-pad k>=585.
// ---------------------------------------------------------------------------
__global__ void repack_b() {
    int kk   = blockIdx.x;
    int t    = threadIdx.x & 31;
    int half = (threadIdx.x >> 5) & 1;
    int ng   = threadIdx.x >> 6;
    int k0 = kk * 8 + (t & 3);
    int k1 = k0 + 4;
    int c0 = ng * 32 + (half * 2 + 0) * 8 + (t >> 2);
    int c1 = ng * 32 + (half * 2 + 1) * 8 + (t >> 2);
    float v0 = (k0 < KTOT) ? g_Wcat[k0 * H_ + c0] : 0.f;
    float v1 = (k1 < KTOT) ? g_Wcat[k1 * H_ + c0] : 0.f;
    float v2 = (k0 < KTOT) ? g_Wcat[k0 * H_ + c1] : 0.f;
    float v3 = (k1 < KTOT) ? g_Wcat[k1 * H_ + c1] : 0.f;
    g_Bpack[((kk * 4 + ng) * 2 + half) * 32 + t] =
        make_uint4(f2tf32(v0), f2tf32(v1), f2tf32(v2), f2tf32(v3));
}

// ---------------------------------------------------------------------------
// Kernel B: main kernel. One block per 2 batch elements, 512 threads.
// All A entries stored PRE-ROUNDED to tf32 -> zero cvt in GEMM/agg loads.
// Ends at max-pool; writes g_pooled.
// ---------------------------------------------------------------------------
struct SmemM {
    float    A[KPAD][ASTR];          // 175104 B, k-major: A[k][m], m = q*32+j
    uint4    Bbuf[2][4][4][2][32];   // 32768 B: [buf][kkl][ng][half][t]
    unsigned masks[512];             // [q*256 + e*32 + j], bit i = A[b,e,i,j]
    float    cinv[512];
    float    pooled2[4][H_];         // per-m16-tile maxima
};

__global__ __launch_bounds__(512, 1) void critic_main(
    const float* __restrict__ unary,    // [B,N,F]
    const int*   __restrict__ binary)   // [B,N,N,E]
{
    extern __shared__ char raw[];
    SmemM& s = *reinterpret_cast<SmemM*>(raw);

    const int tid  = threadIdx.x;
    const int lane = tid & 31;
    const int w    = tid >> 5;          // 16 warps
    const int bg0  = blockIdx.x * 2;    // first batch of this CTA

    // ---- u -> A root rows (pre-rounded tf32): A[512+d][q*32+j] = u[q][j][d] ----
    {
        const float* up = unary + (size_t)bg0 * (N_ * F_);
        #pragma unroll
        for (int p = 0; p < 8; ++p) {
            int li = tid + p * 512;            // 4096 elements
            int q  = li >> 11;
            int j  = (li >> 6) & 31;
            int d  = li & 63;
            s.A[512 + d][q * 32 + j] = __uint_as_float(f2tf32(up[li]));
        }
    }
    s.masks[tid] = 0u;
    __syncthreads();

    // ---- binary -> bitmasks. Thread tid covers fixed (j, e-half); bit
    // i = (tid>>6) + 8*(p&3), batch q = p>>2. OR bits in registers, then
    // <=8 unconditional atomicOr (was <=32 conditional). ----
    {
        const int4* bb = reinterpret_cast<const int4*>(binary + (size_t)bg0 * (N_ * N_ * E_));
        const int j  = (tid >> 1) & 31;
        const int e0 = (tid & 1) * 4;
        const int ib = tid >> 6;
        unsigned acc[2][4];
        #pragma unroll
        for (int q = 0; q < 2; ++q)
            #pragma unroll
            for (int sl = 0; sl < 4; ++sl) acc[q][sl] = 0u;
        #pragma unroll
        for (int p = 0; p < 8; ++p) {
            int4 v = bb[tid + p * 512];
            int q = p >> 2;
            unsigned bit = 1u << ((ib + 8 * (p & 3)) & 31);
            if (v.x) acc[q][0] |= bit;
            if (v.y) acc[q][1] |= bit;
            if (v.z) acc[q][2] |= bit;
            if (v.w) acc[q][3] |= bit;
        }
        #pragma unroll
        for (int q = 0; q < 2; ++q)
            #pragma unroll
            for (int sl = 0; sl < 4; ++sl)
                atomicOr(&s.masks[q * 256 + (e0 + sl) * 32 + j], acc[q][sl]);
    }

    // ---- prefetch B chunks 0 and 1 ----
    {
        const uint4* src = g_Bpack;
        uint4* dst0 = &s.Bbuf[0][0][0][0][0];
        uint4* dst1 = &s.Bbuf[1][0][0][0][0];
        cp16(dst0 + tid, src + tid);
        cp16(dst0 + tid + 512, src + tid + 512);
        asm volatile("cp.async.commit_group;" ::: "memory");
        cp16(dst1 + tid, src + 1024 + tid);
        cp16(dst1 + tid + 512, src + 1024 + tid + 512);
        asm volatile("cp.async.commit_group;" ::: "memory");
    }
    __syncthreads();

    { int d = __popc(s.masks[tid]); s.cinv[tid] = d ? (1.0f / (float)d) : 0.0f; }
    __syncthreads();

    // ========================================================================
    // Tensor-core aggregation: S_e[j][d] = sum_i adj_e[i,j] * u[i,d].
    // A-op = adjacency bits ({0,1} exact), B-op = pre-rounded u (raw bits).
    // Output scaled by cinv, rounded to tf32, stored to A rows 0..511.
    // ========================================================================
    {
        const int gr = lane >> 2, gc = lane & 3;
        const int q  = w >> 3;
        const int mt = (w >> 2) & 1;
        const int np = w & 3;

        uint32_t uf[2][4][2];     // [nt2][kb][b0/b1]
        #pragma unroll
        for (int nt2 = 0; nt2 < 2; ++nt2) {
            int nt = np * 2 + nt2;
            #pragma unroll
            for (int kb = 0; kb < 4; ++kb) {
                uf[nt2][kb][0] = __float_as_uint(s.A[512 + nt * 8 + gr][q * 32 + kb * 8 + gc]);
                uf[nt2][kb][1] = __float_as_uint(s.A[512 + nt * 8 + gr][q * 32 + kb * 8 + gc + 4]);
            }
        }
        const int mcol = q * 32 + mt * 16 + gr;
        #pragma unroll
        for (int e = 0; e < E_; ++e) {
            const int mb = q * 256 + e * 32 + mt * 16 + gr;
            unsigned mr0 = s.masks[mb];
            unsigned mr1 = s.masks[mb + 8];
            float ci0 = s.cinv[mb];
            float ci1 = s.cinv[mb + 8];
            float acc0[4] = {0.f, 0.f, 0.f, 0.f};
            float acc1[4] = {0.f, 0.f, 0.f, 0.f};
            #pragma unroll
            for (int kb = 0; kb < 4; ++kb) {
                int bi = kb * 8 + gc;
                uint32_t ar[4];
                ar[0] = ((mr0 >> bi) & 1u)       ? 0x3f800000u : 0u;
                ar[1] = ((mr1 >> bi) & 1u)       ? 0x3f800000u : 0u;
                ar[2] = ((mr0 >> (bi + 4)) & 1u) ? 0x3f800000u : 0u;
                ar[3] = ((mr1 >> (bi + 4)) & 1u) ? 0x3f800000u : 0u;
                mma_tf32(acc0, ar, uf[0][kb][0], uf[0][kb][1]);
                mma_tf32(acc1, ar, uf[1][kb][0], uf[1][kb][1]);
            }
            {
                int row = e * 64 + (np * 2 + 0) * 8 + 2 * gc;
                s.A[row][mcol]         = __uint_as_float(f2tf32(acc0[0] * ci0));
                s.A[row + 1][mcol]     = __uint_as_float(f2tf32(acc0[1] * ci0));
                s.A[row][mcol + 8]     = __uint_as_float(f2tf32(acc0[2] * ci1));
                s.A[row + 1][mcol + 8] = __uint_as_float(f2tf32(acc0[3] * ci1));
            }
            {
                int row = e * 64 + (np * 2 + 1) * 8 + 2 * gc;
                s.A[row][mcol]         = __uint_as_float(f2tf32(acc1[0] * ci0));
                s.A[row + 1][mcol]     = __uint_as_float(f2tf32(acc1[1] * ci0));
                s.A[row][mcol + 8]     = __uint_as_float(f2tf32(acc1[2] * ci1));
                s.A[row + 1][mcol + 8] = __uint_as_float(f2tf32(acc1[3] * ci1));
            }
        }
    }
    // special k-rows (exact in tf32): 576..583 deg>0, 584 ones, 585..607 zeros
    {
        int q2 = tid >> 8, e2 = (tid >> 5) & 7, j2 = tid & 31;
        s.A[576 + e2][q2 * 32 + j2] = s.masks[tid] ? 1.0f : 0.0f;
        if (tid < 64) s.A[584][tid] = 1.0f;
        for (int r = tid; r < 23 * 64; r += 512)
            s.A[585 + (r >> 6)][r & 63] = 0.0f;
    }
    __syncthreads();   // A fully ready

    // ========================================================================
    // Main GEMM: C[m][n] = sum_k A[k][m] * Wcat[k][n], tf32 tensor cores.
    // A loads are raw bit moves (pre-rounded) -> no cvt in the loop.
    // ========================================================================
    const int mw = w & 3;
    const int ng = w >> 2;
    const int fc = lane & 3;
    const int fr = lane >> 2;
    const int m0 = mw * 16;

    float acc[4][4];
    #pragma unroll
    for (int nt = 0; nt < 4; ++nt)
        #pragma unroll
        for (int i = 0; i < 4; ++i) acc[nt][i] = 0.0f;

    for (int ch = 0; ch < NCHUNK; ++ch) {
        asm volatile("cp.async.wait_group 1;" ::: "memory");
        __syncthreads();
        #pragma unroll
        for (int kkl = 0; kkl < 4; ++kkl) {
            const int k0 = (ch * 4 + kkl) * 8;
            uint32_t a[4];
            a[0] = __float_as_uint(s.A[k0 + fc][m0 + fr]);
            a[1] = __float_as_uint(s.A[k0 + fc][m0 + fr + 8]);
            a[2] = __float_as_uint(s.A[k0 + fc + 4][m0 + fr]);
            a[3] = __float_as_uint(s.A[k0 + fc + 4][m0 + fr + 8]);
            uint4 lo = s.Bbuf[ch & 1][kkl][ng][0][lane];
            uint4 hi = s.Bbuf[ch & 1][kkl][ng][1][lane];
            mma_tf32(acc[0], a, lo.x, lo.y);
            mma_tf32(acc[1], a, lo.z, lo.w);
            mma_tf32(acc[2], a, hi.x, hi.y);
            mma_tf32(acc[3], a, hi.z, hi.w);
        }
        __syncthreads();
        if (ch + 2 < NCHUNK) {
            const uint4* src = g_Bpack + (size_t)(ch + 2) * 1024;
            uint4* dst = &s.Bbuf[ch & 1][0][0][0][0];
            cp16(dst + tid, src + tid);
            cp16(dst + tid + 512, src + tid + 512);
            asm volatile("cp.async.commit_group;" ::: "memory");
        }
    }

    // ---- relu + max-pool over nodes ----
    #pragma unroll
    for (int nt = 0; nt < 4; ++nt) {
        float v0 = fmaxf(fmaxf(acc[nt][0], acc[nt][2]), 0.0f);
        float v1 = fmaxf(fmaxf(acc[nt][1], acc[nt][3]), 0.0f);
        #pragma unroll
        for (int off = 4; off < 32; off <<= 1) {
            v0 = fmaxf(v0, __shfl_xor_sync(0xffffffffu, v0, off));
            v1 = fmaxf(v1, __shfl_xor_sync(0xffffffffu, v1, off));
        }
        if (lane < 4) {
            int cb = ng * 32 + nt * 8 + 2 * lane;
            s.pooled2[mw][cb]     = v0;
            s.pooled2[mw][cb + 1] = v1;
        }
    }
    __syncthreads();
    if (tid < 256) {
        int q = tid >> 7, h = tid & 127;
        g_pooled[(size_t)(bg0 + q) * H_ + h] =
            fmaxf(s.pooled2[2 * q][h], s.pooled2[2 * q + 1][h]);
    }
}

// ---------------------------------------------------------------------------
// Kernel C: heads. grid = 4 agents x 64 batch-tiles of 32, block 256,
// ~99 KB smem -> 2 CTAs/SM, 256 CTAs (> 148 SMs).
// ---------------------------------------------------------------------------
struct SmemH {
    float P[32][H_];      // pooled tile     16384 B
    float W[H_][H_];      // W1[a]           65536 B
    float Z[32][132];     // z (padded rows) 16896 B
    int   cols[32];
};

__global__ __launch_bounds__(256, 2) void heads_kernel(
    const float* __restrict__ actions,  // [NA,B,NACT]
    const float* __restrict__ W1,       // [NA,H,H]
    const float* __restrict__ b1,       // [NA,H]
    const float* __restrict__ W2,       // [NA,H,NACT]
    const float* __restrict__ b2,       // [NA,NACT]
    float* __restrict__ qout)           // [NA,B,1]
{
    extern __shared__ char raw[];
    SmemH& s = *reinterpret_cast<SmemH*>(raw);
    const int tid = threadIdx.x;
    const int a   = blockIdx.x >> 6;
    const int b0  = (blockIdx.x & 63) * 32;

    // stage pooled tile + W1[a]
    {
        const float4* ps = reinterpret_cast<const float4*>(g_pooled + (size_t)b0 * H_);
        float4* pd = reinterpret_cast<float4*>(&s.P[0][0]);
        #pragma unroll
        for (int p = 0; p < 4; ++p) pd[tid + p * 256] = ps[tid + p * 256];
        const float4* ws = reinterpret_cast<const float4*>(W1 + (size_t)a * H_ * H_);
        float4* wd = reinterpret_cast<float4*>(&s.W[0][0]);
        #pragma unroll
        for (int p = 0; p < 16; ++p) wd[tid + p * 256] = ws[tid + p * 256];
    }
    if (tid < 32) {
        const float* ap = actions + ((size_t)a * B_ + b0 + tid) * NACT_;
        float best = ap[0]; int col = 0;
        #pragma unroll
        for (int k = 1; k < NACT_; ++k) {
            float v = ap[k];
            if (v > best) { best = v; col = k; }
        }
        s.cols[tid] = col;
    }
    __syncthreads();

    // z = leaky(P @ W + b1): thread = (bi = tid>>5: 4 batches, hi = tid&31: 4 h)
    {
        const int bi = tid >> 5;
        const int hi = tid & 31;
        float4 bv = *reinterpret_cast<const float4*>(b1 + a * H_ + hi * 4);
        uint64_t zp[4][2];
        #pragma unroll
        for (int r = 0; r < 4; ++r) {
            zp[r][0] = pk2(bv.x, bv.y);
            zp[r][1] = pk2(bv.z, bv.w);
        }
        #pragma unroll 4
        for (int k = 0; k < H_; ++k) {
            float4 wv = *reinterpret_cast<const float4*>(&s.W[k][hi * 4]);
            uint64_t w01 = pk2(wv.x, wv.y);
            uint64_t w23 = pk2(wv.z, wv.w);
            #pragma unroll
            for (int r = 0; r < 4; ++r) {
                float pv = s.P[bi * 4 + r][k];     // warp-uniform broadcast
                uint64_t pv2 = pk2(pv, pv);
                zp[r][0] = fma2(pv2, w01, zp[r][0]);
                zp[r][1] = fma2(pv2, w23, zp[r][1]);
            }
        }
        #pragma unroll
        for (int r = 0; r < 4; ++r) {
            float z0, z1, z2, z3;
            upk2(zp[r][0], z0, z1);
            upk2(zp[r][1], z2, z3);
            z0 = (z0 > 0.f) ? z0 : 0.01f * z0;
            z1 = (z1 > 0.f) ? z1 : 0.01f * z1;
            z2 = (z2 > 0.f) ? z2 : 0.01f * z2;
            z3 = (z3 > 0.f) ? z3 : 0.01f * z3;
            float* zr = &s.Z[bi * 4 + r][hi * 4];
            zr[0] = z0; zr[1] = z1; zr[2] = z2; zr[3] = z3;
        }
    }
    __syncthreads();

    // q = z @ W2[:, col] + b2: thread = (b = tid>>3, qt = tid&7), 16 h each
    {
        const int b  = tid >> 3;
        const int qt = tid & 7;
        const int col = s.cols[b];
        const float* w2p = W2 + (size_t)a * H_ * NACT_ + col;
        float part = 0.f;
        #pragma unroll 8
        for (int i = 0; i < 16; ++i) {
            int h = i * 8 + qt;
            part = fmaf(s.Z[b][h], __ldg(w2p + h * NACT_), part);
        }
        part += __shfl_xor_sync(0xffffffffu, part, 1);
        part += __shfl_xor_sync(0xffffffffu, part, 2);
        part += __shfl_xor_sync(0xffffffffu, part, 4);
        if (qt == 0)
            qout[(size_t)a * B_ + b0 + b] = part + b2[a * NACT_ + col];
    }
}

// ---------------------------------------------------------------------------
extern "C" void kernel_launch(void* const* d_in, const int* in_sizes, int n_in,
                              void* d_out, int out_size) {
    const float* unary   = (const float*)d_in[0];
    const int*   binary  = (const int*)  d_in[1];
    const float* actions = (const float*)d_in[2];
    const float* We      = (const float*)d_in[3];
    const float* be      = (const float*)d_in[4];
    const float* Wrel    = (const float*)d_in[5];
    const float* Wroot   = (const float*)d_in[6];
    const float* brel    = (const float*)d_in[7];
    const float* W1      = (const float*)d_in[8];
    const float* b1      = (const float*)d_in[9];
    const float* W2      = (const float*)d_in[10];
    const float* b2      = (const float*)d_in[11];
    float* qout = (float*)d_out;

    cudaFuncSetAttribute(critic_main, cudaFuncAttributeMaxDynamicSharedMemorySize,
                         (int)sizeof(SmemM));
    cudaFuncSetAttribute(heads_kernel, cudaFuncAttributeMaxDynamicSharedMemorySize,
                         (int)sizeof(SmemH));

    precompute_wcat<<<KTOT, H_>>>(We, be, Wrel, Wroot, brel);
    repack_b<<<KK_, 256>>>();
    critic_main<<<B_ / 2, 512, sizeof(SmemM)>>>(unary, binary);
    heads_kernel<<<NA_ * 64, 256, sizeof(SmemH)>>>(actions, W1, b1, W2, b2, qout);
}

// round 9
// speedup vs baseline: 2.9488x; 1.0913x over previous
#include <cuda_runtime.h>
#include <cstdint>

#define B_    2048
#define N_    32
#define F_    64
#define E_    8
#define H_    128
#define NA_   4
#define NACT_ 16
#define KTOT  585      // 512 agg + 64 root + 8 mask-bias + 1 const-bias
#define KK_   76       // k8 blocks (K padded to 608)
#define KPAD  608
#define ASTR  72       // A smem row stride in floats; 72%32==8 -> conflict-free frags
#define NCHUNK 19      // 19 chunks x 4 k8-blocks

// __device__ scratch (no allocations allowed)
__device__ float g_Wcat[KTOT * H_];            // logical [k][h]
__device__ uint4 g_Bpack[KK_ * 4 * 2 * 32];    // [kk][ng][half][t] fragment-packed tf32
__device__ float g_pooled[B_ * H_];            // [b][h]

static __device__ __forceinline__ uint32_t f2tf32(float f) {
    uint32_t r; asm("cvt.rna.tf32.f32 %0, %1;" : "=r"(r) : "f"(f)); return r;
}
static __device__ __forceinline__ void cp16(void* dst, const void* src) {
    uint32_t d = (uint32_t)__cvta_generic_to_shared(dst);
    asm volatile("cp.async.cg.shared.global [%0], [%1], 16;" :: "r"(d), "l"(src));
}
static __device__ __forceinline__ void mma_tf32(float c[4], const uint32_t a[4],
                                                uint32_t b0, uint32_t b1) {
    asm volatile(
        "mma.sync.aligned.m16n8k8.row.col.f32.tf32.tf32.f32 "
        "{%0,%1,%2,%3},{%4,%5,%6,%7},{%8,%9},{%0,%1,%2,%3};"
        : "+f"(c[0]), "+f"(c[1]), "+f"(c[2]), "+f"(c[3])
        : "r"(a[0]), "r"(a[1]), "r"(a[2]), "r"(a[3]), "r"(b0), "r"(b1));
}
static __device__ __forceinline__ uint64_t pk2(float lo, float hi) {
    uint64_t r; asm("mov.b64 %0, {%1, %2};" : "=l"(r) : "f"(lo), "f"(hi)); return r;
}
static __device__ __forceinline__ void upk2(uint64_t v, float& lo, float& hi) {
    asm("mov.b64 {%0, %1}, %2;" : "=f"(lo), "=f"(hi) : "l"(v));
}
static __device__ __forceinline__ uint64_t fma2(uint64_t a, uint64_t b, uint64_t c) {
    uint64_t d; asm("fma.rn.f32x2 %0, %1, %2, %3;" : "=l"(d) : "l"(a), "l"(b), "l"(c));
    return d;
}

// ---------------------------------------------------------------------------
// Kernel A: fold We/be into Wrel/Wroot/brel -> g_Wcat[585][128]
// ---------------------------------------------------------------------------
__global__ void precompute_wcat(const float* __restrict__ We,
                                const float* __restrict__ be,
                                const float* __restrict__ Wrel,
                                const float* __restrict__ Wroot,
                                const float* __restrict__ brel) {
    __shared__ float vec[H_];
    const int r = blockIdx.x;
    const int h = threadIdx.x;
    const float* Bmat;
    float addv = 0.0f;
    if (r < 512) {
        int e = r >> 6, d = r & 63;
        vec[h] = We[d * H_ + h];
        Bmat = Wrel + e * H_ * H_;
    } else if (r < 576) {
        int d = r - 512;
        vec[h] = We[d * H_ + h];
        Bmat = Wroot;
    } else if (r < 584) {
        int e = r - 576;
        vec[h] = be[h];
        Bmat = Wrel + e * H_ * H_;
    } else {
        vec[h] = be[h];
        Bmat = Wroot;
        addv = brel[h];
    }
    __syncthreads();
    float a0 = 0.f, a1 = 0.f, a2 = 0.f, a3 = 0.f;
    #pragma unroll 8
    for (int t = 0; t < H_; t += 4) {
        a0 = fmaf(vec[t],     __ldg(Bmat + (t    ) * H_ + h), a0);
        a1 = fmaf(vec[t + 1], __ldg(Bmat + (t + 1) * H_ + h), a1);
        a2 = fmaf(vec[t + 2], __ldg(Bmat + (t + 2) * H_ + h), a2);
        a3 = fmaf(vec[t + 3], __ldg(Bmat + (t + 3) * H_ + h), a3);
    }
    g_Wcat[r * H_ + h] = addv + ((a0 + a1) + (a2 + a3));
}

// ---------------------------------------------------------------------------
// Kernel A2: repack g_Wcat into mma B-fragment order (tf32), zero-pad k>=585.
// ---------------------------------------------------------------------------
__global__ void repack_b() {
    int kk   = blockIdx.x;
    int t    = threadIdx.x & 31;
    int half = (threadIdx.x >> 5) & 1;
    int ng   = threadIdx.x >> 6;
    int k0 = kk * 8 + (t & 3);
    int k1 = k0 + 4;
    int c0 = ng * 32 + (half * 2 + 0) * 8 + (t >> 2);
    int c1 = ng * 32 + (half * 2 + 1) * 8 + (t >> 2);
    float v0 = (k0 < KTOT) ? g_Wcat[k0 * H_ + c0] : 0.f;
    float v1 = (k1 < KTOT) ? g_Wcat[k1 * H_ + c0] : 0.f;
    float v2 = (k0 < KTOT) ? g_Wcat[k0 * H_ + c1] : 0.f;
    float v3 = (k1 < KTOT) ? g_Wcat[k1 * H_ + c1] : 0.f;
    g_Bpack[((kk * 4 + ng) * 2 + half) * 32 + t] =
        make_uint4(f2tf32(v0), f2tf32(v1), f2tf32(v2), f2tf32(v3));
}

// ---------------------------------------------------------------------------
// Kernel B: main kernel. One block per 2 batch elements, 512 threads.
// GEMM: warp tile m32 x n64, k-split-4 interleaved across the 4 k8s of each
// chunk -> half the LDS bytes of the m16 x n32 version.
// ---------------------------------------------------------------------------
struct SmemM {
    union AB {
        float A[KPAD][ASTR];         // 175104 B, k-major: A[k][m], m = q*32+j
        float Cpart[4][64][132];     // 135168 B: k-split partials (epilogue)
    } ab;
    uint4    Bbuf[2][4][4][2][32];   // 32768 B: [buf][k8-in-chunk][n32][half][t]
    unsigned masks[512];             // [q*256 + e*32 + j], bit i = A[b,e,i,j]
    float    cinv[512];
};

__global__ __launch_bounds__(512, 1) void critic_main(
    const float* __restrict__ unary,    // [B,N,F]
    const int*   __restrict__ binary)   // [B,N,N,E]
{
    extern __shared__ char raw[];
    SmemM& s = *reinterpret_cast<SmemM*>(raw);

    const int tid  = threadIdx.x;
    const int lane = tid & 31;
    const int w    = tid >> 5;          // 16 warps
    const int bg0  = blockIdx.x * 2;    // first batch of this CTA

    // ---- u -> A root rows (pre-rounded tf32): A[512+d][q*32+j] = u[q][j][d] ----
    {
        const float* up = unary + (size_t)bg0 * (N_ * F_);
        #pragma unroll
        for (int p = 0; p < 8; ++p) {
            int li = tid + p * 512;            // 4096 elements
            int q  = li >> 11;
            int j  = (li >> 6) & 31;
            int d  = li & 63;
            s.ab.A[512 + d][q * 32 + j] = __uint_as_float(f2tf32(up[li]));
        }
    }
    s.masks[tid] = 0u;
    __syncthreads();

    // ---- binary -> bitmasks: register-accumulate then 8 atomicOr ----
    {
        const int4* bb = reinterpret_cast<const int4*>(binary + (size_t)bg0 * (N_ * N_ * E_));
        const int j  = (tid >> 1) & 31;
        const int e0 = (tid & 1) * 4;
        const int ib = tid >> 6;
        unsigned acc[2][4];
        #pragma unroll
        for (int q = 0; q < 2; ++q)
            #pragma unroll
            for (int sl = 0; sl < 4; ++sl) acc[q][sl] = 0u;
        #pragma unroll
        for (int p = 0; p < 8; ++p) {
            int4 v = bb[tid + p * 512];
            int q = p >> 2;
            unsigned bit = 1u << ((ib + 8 * (p & 3)) & 31);
            if (v.x) acc[q][0] |= bit;
            if (v.y) acc[q][1] |= bit;
            if (v.z) acc[q][2] |= bit;
            if (v.w) acc[q][3] |= bit;
        }
        #pragma unroll
        for (int q = 0; q < 2; ++q)
            #pragma unroll
            for (int sl = 0; sl < 4; ++sl)
                atomicOr(&s.masks[q * 256 + (e0 + sl) * 32 + j], acc[q][sl]);
    }

    // ---- prefetch B chunks 0 and 1 ----
    {
        const uint4* src = g_Bpack;
        uint4* dst0 = &s.Bbuf[0][0][0][0][0];
        uint4* dst1 = &s.Bbuf[1][0][0][0][0];
        cp16(dst0 + tid, src + tid);
        cp16(dst0 + tid + 512, src + tid + 512);
        asm volatile("cp.async.commit_group;" ::: "memory");
        cp16(dst1 + tid, src + 1024 + tid);
        cp16(dst1 + tid + 512, src + 1024 + tid + 512);
        asm volatile("cp.async.commit_group;" ::: "memory");
    }
    __syncthreads();

    { int d = __popc(s.masks[tid]); s.cinv[tid] = d ? (1.0f / (float)d) : 0.0f; }
    __syncthreads();

    // ========================================================================
    // Tensor-core aggregation (unchanged from the passing R7 version).
    // ========================================================================
    {
        const int gr = lane >> 2, gc = lane & 3;
        const int q  = w >> 3;
        const int mt = (w >> 2) & 1;
        const int np = w & 3;

        uint32_t uf[2][4][2];     // [nt2][kb][b0/b1]
        #pragma unroll
        for (int nt2 = 0; nt2 < 2; ++nt2) {
            int nt = np * 2 + nt2;
            #pragma unroll
            for (int kb = 0; kb < 4; ++kb) {
                uf[nt2][kb][0] = __float_as_uint(s.ab.A[512 + nt * 8 + gr][q * 32 + kb * 8 + gc]);
                uf[nt2][kb][1] = __float_as_uint(s.ab.A[512 + nt * 8 + gr][q * 32 + kb * 8 + gc + 4]);
            }
        }
        const int mcol = q * 32 + mt * 16 + gr;
        #pragma unroll
        for (int e = 0; e < E_; ++e) {
            const int mb = q * 256 + e * 32 + mt * 16 + gr;
            unsigned mr0 = s.masks[mb];
            unsigned mr1 = s.masks[mb + 8];
            float ci0 = s.cinv[mb];
            float ci1 = s.cinv[mb + 8];
            float acc0[4] = {0.f, 0.f, 0.f, 0.f};
            float acc1[4] = {0.f, 0.f, 0.f, 0.f};
            #pragma unroll
            for (int kb = 0; kb < 4; ++kb) {
                int bi = kb * 8 + gc;
                uint32_t ar[4];
                ar[0] = ((mr0 >> bi) & 1u)       ? 0x3f800000u : 0u;
                ar[1] = ((mr1 >> bi) & 1u)       ? 0x3f800000u : 0u;
                ar[2] = ((mr0 >> (bi + 4)) & 1u) ? 0x3f800000u : 0u;
                ar[3] = ((mr1 >> (bi + 4)) & 1u) ? 0x3f800000u : 0u;
                mma_tf32(acc0, ar, uf[0][kb][0], uf[0][kb][1]);
                mma_tf32(acc1, ar, uf[1][kb][0], uf[1][kb][1]);
            }
            {
                int row = e * 64 + (np * 2 + 0) * 8 + 2 * gc;
                s.ab.A[row][mcol]         = __uint_as_float(f2tf32(acc0[0] * ci0));
                s.ab.A[row + 1][mcol]     = __uint_as_float(f2tf32(acc0[1] * ci0));
                s.ab.A[row][mcol + 8]     = __uint_as_float(f2tf32(acc0[2] * ci1));
                s.ab.A[row + 1][mcol + 8] = __uint_as_float(f2tf32(acc0[3] * ci1));
            }
            {
                int row = e * 64 + (np * 2 + 1) * 8 + 2 * gc;
                s.ab.A[row][mcol]         = __uint_as_float(f2tf32(acc1[0] * ci0));
                s.ab.A[row + 1][mcol]     = __uint_as_float(f2tf32(acc1[1] * ci0));
                s.ab.A[row][mcol + 8]     = __uint_as_float(f2tf32(acc1[2] * ci1));
                s.ab.A[row + 1][mcol + 8] = __uint_as_float(f2tf32(acc1[3] * ci1));
            }
        }
    }
    // special k-rows (exact in tf32): 576..583 deg>0, 584 ones, 585..607 zeros
    {
        int q2 = tid >> 8, e2 = (tid >> 5) & 7, j2 = tid & 31;
        s.ab.A[576 + e2][q2 * 32 + j2] = s.masks[tid] ? 1.0f : 0.0f;
        if (tid < 64) s.ab.A[584][tid] = 1.0f;
        for (int r = tid; r < 23 * 64; r += 512)
            s.ab.A[585 + (r >> 6)][r & 63] = 0.0f;
    }
    __syncthreads();   // A fully ready

    // ========================================================================
    // Main GEMM: warp = (mw2 = w&1: m32 tile, ngp = (w>>1)&1: n64 group,
    // ks = w>>2: k8-within-chunk). Each warp does ONE k8 per chunk.
    // Per chunk per warp: 8 scalar A-LDS + 4 B-LDS.128 + 16 mma.
    // ========================================================================
    const int mw2 = w & 1;
    const int ngp = (w >> 1) & 1;
    const int ks  = w >> 2;
    const int fc  = lane & 3;
    const int fr  = lane >> 2;
    const int m0  = mw2 * 32;

    float acc[2][8][4];
    #pragma unroll
    for (int mt2 = 0; mt2 < 2; ++mt2)
        #pragma unroll
        for (int nn = 0; nn < 8; ++nn)
            #pragma unroll
            for (int i = 0; i < 4; ++i) acc[mt2][nn][i] = 0.0f;

    for (int ch = 0; ch < NCHUNK; ++ch) {
        asm volatile("cp.async.wait_group 1;" ::: "memory");
        __syncthreads();
        const int k0 = (ch * 4 + ks) * 8;
        uint32_t a0[4], a1[4];
        a0[0] = __float_as_uint(s.ab.A[k0 + fc][m0 + fr]);
        a0[1] = __float_as_uint(s.ab.A[k0 + fc][m0 + fr + 8]);
        a0[2] = __float_as_uint(s.ab.A[k0 + fc + 4][m0 + fr]);
        a0[3] = __float_as_uint(s.ab.A[k0 + fc + 4][m0 + fr + 8]);
        a1[0] = __float_as_uint(s.ab.A[k0 + fc][m0 + 16 + fr]);
        a1[1] = __float_as_uint(s.ab.A[k0 + fc][m0 + 16 + fr + 8]);
        a1[2] = __float_as_uint(s.ab.A[k0 + fc + 4][m0 + 16 + fr]);
        a1[3] = __float_as_uint(s.ab.A[k0 + fc + 4][m0 + 16 + fr + 8]);
        #pragma unroll
        for (int ngl = 0; ngl < 2; ++ngl) {
            const int n32 = ngp * 2 + ngl;
            uint4 lo = s.Bbuf[ch & 1][ks][n32][0][lane];
            uint4 hi = s.Bbuf[ch & 1][ks][n32][1][lane];
            mma_tf32(acc[0][ngl * 4 + 0], a0, lo.x, lo.y);
            mma_tf32(acc[0][ngl * 4 + 1], a0, lo.z, lo.w);
            mma_tf32(acc[0][ngl * 4 + 2], a0, hi.x, hi.y);
            mma_tf32(acc[0][ngl * 4 + 3], a0, hi.z, hi.w);
            mma_tf32(acc[1][ngl * 4 + 0], a1, lo.x, lo.y);
            mma_tf32(acc[1][ngl * 4 + 1], a1, lo.z, lo.w);
            mma_tf32(acc[1][ngl * 4 + 2], a1, hi.x, hi.y);
            mma_tf32(acc[1][ngl * 4 + 3], a1, hi.z, hi.w);
        }
        __syncthreads();
        if (ch + 2 < NCHUNK) {
            const uint4* src = g_Bpack + (size_t)(ch + 2) * 1024;
            uint4* dst = &s.Bbuf[ch & 1][0][0][0][0];
            cp16(dst + tid, src + tid);
            cp16(dst + tid + 512, src + tid + 512);
            asm volatile("cp.async.commit_group;" ::: "memory");
        }
    }

    // ---- store k-split partials (A region is dead now) ----
    __syncthreads();
    {
        float* Cp = &s.ab.Cpart[ks][0][0];
        #pragma unroll
        for (int mt2 = 0; mt2 < 2; ++mt2) {
            const int row = m0 + mt2 * 16 + fr;
            #pragma unroll
            for (int nn = 0; nn < 8; ++nn) {
                const int col = ngp * 64 + nn * 8 + 2 * fc;
                Cp[row * 132 + col]           = acc[mt2][nn][0];
                Cp[row * 132 + col + 1]       = acc[mt2][nn][1];
                Cp[(row + 8) * 132 + col]     = acc[mt2][nn][2];
                Cp[(row + 8) * 132 + col + 1] = acc[mt2][nn][3];
            }
        }
    }
    __syncthreads();

    // ---- merge partials + relu + max-pool over nodes ----
    if (tid < 256) {
        const int q = tid >> 7, h = tid & 127;
        float mx = -3.0e38f;
        #pragma unroll 4
        for (int j = 0; j < N_; ++j) {
            const int row = q * 32 + j;
            float v = s.ab.Cpart[0][row][h] + s.ab.Cpart[1][row][h]
                    + s.ab.Cpart[2][row][h] + s.ab.Cpart[3][row][h];
            mx = fmaxf(mx, v);
        }
        g_pooled[(size_t)(bg0 + q) * H_ + h] = fmaxf(mx, 0.0f);
    }
}

// ---------------------------------------------------------------------------
// Kernel C: heads (unchanged from passing R7 version).
// ---------------------------------------------------------------------------
struct SmemH {
    float P[32][H_];
    float W[H_][H_];
    float Z[32][132];
    int   cols[32];
};

__global__ __launch_bounds__(256, 2) void heads_kernel(
    const float* __restrict__ actions,
    const float* __restrict__ W1,
    const float* __restrict__ b1,
    const float* __restrict__ W2,
    const float* __restrict__ b2,
    float* __restrict__ qout)
{
    extern __shared__ char raw[];
    SmemH& s = *reinterpret_cast<SmemH*>(raw);
    const int tid = threadIdx.x;
    const int a   = blockIdx.x >> 6;
    const int b0  = (blockIdx.x & 63) * 32;

    {
        const float4* ps = reinterpret_cast<const float4*>(g_pooled + (size_t)b0 * H_);
        float4* pd = reinterpret_cast<float4*>(&s.P[0][0]);
        #pragma unroll
        for (int p = 0; p < 4; ++p) pd[tid + p * 256] = ps[tid + p * 256];
        const float4* ws = reinterpret_cast<const float4*>(W1 + (size_t)a * H_ * H_);
        float4* wd = reinterpret_cast<float4*>(&s.W[0][0]);
        #pragma unroll
        for (int p = 0; p < 16; ++p) wd[tid + p * 256] = ws[tid + p * 256];
    }
    if (tid < 32) {
        const float* ap = actions + ((size_t)a * B_ + b0 + tid) * NACT_;
        float best = ap[0]; int col = 0;
        #pragma unroll
        for (int k = 1; k < NACT_; ++k) {
            float v = ap[k];
            if (v > best) { best = v; col = k; }
        }
        s.cols[tid] = col;
    }
    __syncthreads();
    {
        const int bi = tid >> 5;
        const int hi = tid & 31;
        float4 bv = *reinterpret_cast<const float4*>(b1 + a * H_ + hi * 4);
        uint64_t zp[4][2];
        #pragma unroll
        for (int r = 0; r < 4; ++r) {
            zp[r][0] = pk2(bv.x, bv.y);
            zp[r][1] = pk2(bv.z, bv.w);
        }
        #pragma unroll 4
        for (int k = 0; k < H_; ++k) {
            float4 wv = *reinterpret_cast<const float4*>(&s.W[k][hi * 4]);
            uint64_t w01 = pk2(wv.x, wv.y);
            uint64_t w23 = pk2(wv.z, wv.w);
            #pragma unroll
            for (int r = 0; r < 4; ++r) {
                float pv = s.P[bi * 4 + r][k];
                uint64_t pv2 = pk2(pv, pv);
                zp[r][0] = fma2(pv2, w01, zp[r][0]);
                zp[r][1] = fma2(pv2, w23, zp[r][1]);
            }
        }
        #pragma unroll
        for (int r = 0; r < 4; ++r) {
            float z0, z1, z2, z3;
            upk2(zp[r][0], z0, z1);
            upk2(zp[r][1], z2, z3);
            z0 = (z0 > 0.f) ? z0 : 0.01f * z0;
            z1 = (z1 > 0.f) ? z1 : 0.01f * z1;
            z2 = (z2 > 0.f) ? z2 : 0.01f * z2;
            z3 = (z3 > 0.f) ? z3 : 0.01f * z3;
            float* zr = &s.Z[bi * 4 + r][hi * 4];
            zr[0] = z0; zr[1] = z1; zr[2] = z2; zr[3] = z3;
        }
    }
    __syncthreads();
    {
        const int b  = tid >> 3;
        const int qt = tid & 7;
        const int col = s.cols[b];
        const float* w2p = W2 + (size_t)a * H_ * NACT_ + col;
        float part = 0.f;
        #pragma unroll 8
        for (int i = 0; i < 16; ++i) {
            int h = i * 8 + qt;
            part = fmaf(s.Z[b][h], __ldg(w2p + h * NACT_), part);
        }
        part += __shfl_xor_sync(0xffffffffu, part, 1);
        part += __shfl_xor_sync(0xffffffffu, part, 2);
        part += __shfl_xor_sync(0xffffffffu, part, 4);
        if (qt == 0)
            qout[(size_t)a * B_ + b0 + b] = part + b2[a * NACT_ + col];
    }
}

// ---------------------------------------------------------------------------
extern "C" void kernel_launch(void* const* d_in, const int* in_sizes, int n_in,
                              void* d_out, int out_size) {
    const float* unary   = (const float*)d_in[0];
    const int*   binary  = (const int*)  d_in[1];
    const float* actions = (const float*)d_in[2];
    const float* We      = (const float*)d_in[3];
    const float* be      = (const float*)d_in[4];
    const float* Wrel    = (const float*)d_in[5];
    const float* Wroot   = (const float*)d_in[6];
    const float* brel    = (const float*)d_in[7];
    const float* W1      = (const float*)d_in[8];
    const float* b1      = (const float*)d_in[9];
    const float* W2      = (const float*)d_in[10];
    const float* b2      = (const float*)d_in[11];
    float* qout = (float*)d_out;

    cudaFuncSetAttribute(critic_main, cudaFuncAttributeMaxDynamicSharedMemorySize,
                         (int)sizeof(SmemM));
    cudaFuncSetAttribute(heads_kernel, cudaFuncAttributeMaxDynamicSharedMemorySize,
                         (int)sizeof(SmemH));

    precompute_wcat<<<KTOT, H_>>>(We, be, Wrel, Wroot, brel);
    repack_b<<<KK_, 256>>>();
    critic_main<<<B_ / 2, 512, sizeof(SmemM)>>>(unary, binary);
    heads_kernel<<<NA_ * 64, 256, sizeof(SmemH)>>>(actions, W1, b1, W2, b2, qout);
}

// round 10
// speedup vs baseline: 3.5449x; 1.2021x over previous
#include <cuda_runtime.h>
#include <cstdint>

#define B_    2048
#define N_    32
#define F_    64
#define E_    8
#define H_    128
#define NA_   4
#define NACT_ 16
#define KTOT  585      // 512 agg + 64 root + 8 mask-bias + 1 const-bias
#define KK_   76       // k8 blocks (K padded to 608)
#define KPAD  608
#define ASTR  72       // A smem row stride in floats; 72%32==8 -> conflict-free frags
#define NCHUNK 19      // 19 chunks x 4 k8-blocks

// __device__ scratch (no allocations allowed)
__device__ float g_Wcat[KTOT * H_];            // logical [k][h]
__device__ uint4 g_Bpack[KK_ * 4 * 2 * 32];    // [kk][ng][half][t] fragment-packed tf32
__device__ float g_pooled[B_ * H_];            // [b][h]

static __device__ __forceinline__ uint32_t f2tf32(float f) {
    uint32_t r; asm("cvt.rna.tf32.f32 %0, %1;" : "=r"(r) : "f"(f)); return r;
}
static __device__ __forceinline__ void mma_tf32(float c[4], const uint32_t a[4],
                                                uint32_t b0, uint32_t b1) {
    asm volatile(
        "mma.sync.aligned.m16n8k8.row.col.f32.tf32.tf32.f32 "
        "{%0,%1,%2,%3},{%4,%5,%6,%7},{%8,%9},{%0,%1,%2,%3};"
        : "+f"(c[0]), "+f"(c[1]), "+f"(c[2]), "+f"(c[3])
        : "r"(a[0]), "r"(a[1]), "r"(a[2]), "r"(a[3]), "r"(b0), "r"(b1));
}
static __device__ __forceinline__ uint64_t pk2(float lo, float hi) {
    uint64_t r; asm("mov.b64 %0, {%1, %2};" : "=l"(r) : "f"(lo), "f"(hi)); return r;
}
static __device__ __forceinline__ void upk2(uint64_t v, float& lo, float& hi) {
    asm("mov.b64 {%0, %1}, %2;" : "=f"(lo), "=f"(hi) : "l"(v));
}
static __device__ __forceinline__ uint64_t fma2(uint64_t a, uint64_t b, uint64_t c) {
    uint64_t d; asm("fma.rn.f32x2 %0, %1, %2, %3;" : "=l"(d) : "l"(a), "l"(b), "l"(c));
    return d;
}

// ---------------------------------------------------------------------------
// Kernel A: fold We/be into Wrel/Wroot/brel -> g_Wcat[585][128]
// ---------------------------------------------------------------------------
__global__ void precompute_wcat(const float* __restrict__ We,
                                const float* __restrict__ be,
                                const float* __restrict__ Wrel,
                                const float* __restrict__ Wroot,
                                const float* __restrict__ brel) {
    __shared__ float vec[H_];
    const int r = blockIdx.x;
    const int h = threadIdx.x;
    const float* Bmat;
    float addv = 0.0f;
    if (r < 512) {
        int e = r >> 6, d = r & 63;
        vec[h] = We[d * H_ + h];
        Bmat = Wrel + e * H_ * H_;
    } else if (r < 576) {
        int d = r - 512;
        vec[h] = We[d * H_ + h];
        Bmat = Wroot;
    } else if (r < 584) {
        int e = r - 576;
        vec[h] = be[h];
        Bmat = Wrel + e * H_ * H_;
    } else {
        vec[h] = be[h];
        Bmat = Wroot;
        addv = brel[h];
    }
    __syncthreads();
    float a0 = 0.f, a1 = 0.f, a2 = 0.f, a3 = 0.f;
    #pragma unroll 8
    for (int t = 0; t < H_; t += 4) {
        a0 = fmaf(vec[t],     __ldg(Bmat + (t    ) * H_ + h), a0);
        a1 = fmaf(vec[t + 1], __ldg(Bmat + (t + 1) * H_ + h), a1);
        a2 = fmaf(vec[t + 2], __ldg(Bmat + (t + 2) * H_ + h), a2);
        a3 = fmaf(vec[t + 3], __ldg(Bmat + (t + 3) * H_ + h), a3);
    }
    g_Wcat[r * H_ + h] = addv + ((a0 + a1) + (a2 + a3));
}

// ---------------------------------------------------------------------------
// Kernel A2: repack g_Wcat into mma B-fragment order (tf32), zero-pad k>=585.
// ---------------------------------------------------------------------------
__global__ void repack_b() {
    int kk   = blockIdx.x;
    int t    = threadIdx.x & 31;
    int half = (threadIdx.x >> 5) & 1;
    int ng   = threadIdx.x >> 6;
    int k0 = kk * 8 + (t & 3);
    int k1 = k0 + 4;
    int c0 = ng * 32 + (half * 2 + 0) * 8 + (t >> 2);
    int c1 = ng * 32 + (half * 2 + 1) * 8 + (t >> 2);
    float v0 = (k0 < KTOT) ? g_Wcat[k0 * H_ + c0] : 0.f;
    float v1 = (k1 < KTOT) ? g_Wcat[k1 * H_ + c0] : 0.f;
    float v2 = (k0 < KTOT) ? g_Wcat[k0 * H_ + c1] : 0.f;
    float v3 = (k1 < KTOT) ? g_Wcat[k1 * H_ + c1] : 0.f;
    g_Bpack[((kk * 4 + ng) * 2 + half) * 32 + t] =
        make_uint4(f2tf32(v0), f2tf32(v1), f2tf32(v2), f2tf32(v3));
}

// ---------------------------------------------------------------------------
// Kernel B: main kernel. One block per 2 batch elements, 512 threads.
// GEMM: warp tile m32 x n64, k-split-4. B fragments are read DIRECTLY from
// L2-resident g_Bpack via __ldg with a depth-1 register pipeline ->
// the 19-chunk mainloop has NO barriers and NO smem B staging.
// ---------------------------------------------------------------------------
struct SmemM {
    union AB {
        float A[KPAD][ASTR];         // 175104 B, k-major: A[k][m], m = q*32+j
        float Cpart[4][64][132];     // 135168 B: k-split partials (epilogue)
    } ab;
    unsigned masks[512];             // [q*256 + e*32 + j], bit i = A[b,e,i,j]
    float    cinv[512];
};

__global__ __launch_bounds__(512, 1) void critic_main(
    const float* __restrict__ unary,    // [B,N,F]
    const int*   __restrict__ binary)   // [B,N,N,E]
{
    extern __shared__ char raw[];
    SmemM& s = *reinterpret_cast<SmemM*>(raw);

    const int tid  = threadIdx.x;
    const int lane = tid & 31;
    const int w    = tid >> 5;          // 16 warps
    const int bg0  = blockIdx.x * 2;    // first batch of this CTA

    // ---- u -> A root rows (pre-rounded tf32): A[512+d][q*32+j] = u[q][j][d] ----
    {
        const float* up = unary + (size_t)bg0 * (N_ * F_);
        #pragma unroll
        for (int p = 0; p < 8; ++p) {
            int li = tid + p * 512;            // 4096 elements
            int q  = li >> 11;
            int j  = (li >> 6) & 31;
            int d  = li & 63;
            s.ab.A[512 + d][q * 32 + j] = __uint_as_float(f2tf32(up[li]));
        }
    }
    s.masks[tid] = 0u;
    __syncthreads();

    // ---- binary -> bitmasks: register-accumulate then 8 atomicOr ----
    {
        const int4* bb = reinterpret_cast<const int4*>(binary + (size_t)bg0 * (N_ * N_ * E_));
        const int j  = (tid >> 1) & 31;
        const int e0 = (tid & 1) * 4;
        const int ib = tid >> 6;
        unsigned acc[2][4];
        #pragma unroll
        for (int q = 0; q < 2; ++q)
            #pragma unroll
            for (int sl = 0; sl < 4; ++sl) acc[q][sl] = 0u;
        #pragma unroll
        for (int p = 0; p < 8; ++p) {
            int4 v = bb[tid + p * 512];
            int q = p >> 2;
            unsigned bit = 1u << ((ib + 8 * (p & 3)) & 31);
            if (v.x) acc[q][0] |= bit;
            if (v.y) acc[q][1] |= bit;
            if (v.z) acc[q][2] |= bit;
            if (v.w) acc[q][3] |= bit;
        }
        #pragma unroll
        for (int q = 0; q < 2; ++q)
            #pragma unroll
            for (int sl = 0; sl < 4; ++sl)
                atomicOr(&s.masks[q * 256 + (e0 + sl) * 32 + j], acc[q][sl]);
    }
    __syncthreads();

    { int d = __popc(s.masks[tid]); s.cinv[tid] = d ? (1.0f / (float)d) : 0.0f; }
    __syncthreads();

    // ========================================================================
    // Tensor-core aggregation (unchanged from the passing R9 version).
    // ========================================================================
    {
        const int gr = lane >> 2, gc = lane & 3;
        const int q  = w >> 3;
        const int mt = (w >> 2) & 1;
        const int np = w & 3;

        uint32_t uf[2][4][2];     // [nt2][kb][b0/b1]
        #pragma unroll
        for (int nt2 = 0; nt2 < 2; ++nt2) {
            int nt = np * 2 + nt2;
            #pragma unroll
            for (int kb = 0; kb < 4; ++kb) {
                uf[nt2][kb][0] = __float_as_uint(s.ab.A[512 + nt * 8 + gr][q * 32 + kb * 8 + gc]);
                uf[nt2][kb][1] = __float_as_uint(s.ab.A[512 + nt * 8 + gr][q * 32 + kb * 8 + gc + 4]);
            }
        }
        const int mcol = q * 32 + mt * 16 + gr;
        #pragma unroll
        for (int e = 0; e < E_; ++e) {
            const int mb = q * 256 + e * 32 + mt * 16 + gr;
            unsigned mr0 = s.masks[mb];
            unsigned mr1 = s.masks[mb + 8];
            float ci0 = s.cinv[mb];
            float ci1 = s.cinv[mb + 8];
            float acc0[4] = {0.f, 0.f, 0.f, 0.f};
            float acc1[4] = {0.f, 0.f, 0.f, 0.f};
            #pragma unroll
            for (int kb = 0; kb < 4; ++kb) {
                int bi = kb * 8 + gc;
                uint32_t ar[4];
                ar[0] = ((mr0 >> bi) & 1u)       ? 0x3f800000u : 0u;
                ar[1] = ((mr1 >> bi) & 1u)       ? 0x3f800000u : 0u;
                ar[2] = ((mr0 >> (bi + 4)) & 1u) ? 0x3f800000u : 0u;
                ar[3] = ((mr1 >> (bi + 4)) & 1u) ? 0x3f800000u : 0u;
                mma_tf32(acc0, ar, uf[0][kb][0], uf[0][kb][1]);
                mma_tf32(acc1, ar, uf[1][kb][0], uf[1][kb][1]);
            }
            {
                int row = e * 64 + (np * 2 + 0) * 8 + 2 * gc;
                s.ab.A[row][mcol]         = __uint_as_float(f2tf32(acc0[0] * ci0));
                s.ab.A[row + 1][mcol]     = __uint_as_float(f2tf32(acc0[1] * ci0));
                s.ab.A[row][mcol + 8]     = __uint_as_float(f2tf32(acc0[2] * ci1));
                s.ab.A[row + 1][mcol + 8] = __uint_as_float(f2tf32(acc0[3] * ci1));
            }
            {
                int row = e * 64 + (np * 2 + 1) * 8 + 2 * gc;
                s.ab.A[row][mcol]         = __uint_as_float(f2tf32(acc1[0] * ci0));
                s.ab.A[row + 1][mcol]     = __uint_as_float(f2tf32(acc1[1] * ci0));
                s.ab.A[row][mcol + 8]     = __uint_as_float(f2tf32(acc1[2] * ci1));
                s.ab.A[row + 1][mcol + 8] = __uint_as_float(f2tf32(acc1[3] * ci1));
            }
        }
    }
    // special k-rows (exact in tf32): 576..583 deg>0, 584 ones, 585..607 zeros
    {
        int q2 = tid >> 8, e2 = (tid >> 5) & 7, j2 = tid & 31;
        s.ab.A[576 + e2][q2 * 32 + j2] = s.masks[tid] ? 1.0f : 0.0f;
        if (tid < 64) s.ab.A[584][tid] = 1.0f;
        for (int r = tid; r < 23 * 64; r += 512)
            s.ab.A[585 + (r >> 6)][r & 63] = 0.0f;
    }
    __syncthreads();   // A fully ready; no more barriers until epilogue

    // ========================================================================
    // Main GEMM: warp = (mw2 = w&1: m32 tile, ngp = (w>>1)&1: n64 group,
    // ks = w>>2: k8-within-chunk). B direct from L2 (__ldg), depth-1 prefetch.
    // ========================================================================
    const int mw2 = w & 1;
    const int ngp = (w >> 1) & 1;
    const int ks  = w >> 2;
    const int fc  = lane & 3;
    const int fr  = lane >> 2;
    const int m0  = mw2 * 32;

    float acc[2][8][4];
    #pragma unroll
    for (int mt2 = 0; mt2 < 2; ++mt2)
        #pragma unroll
        for (int nn = 0; nn < 8; ++nn)
            #pragma unroll
            for (int i = 0; i < 4; ++i) acc[mt2][nn][i] = 0.0f;

    // B fragment pointer for this warp: [kk = ch*4+ks][ng = ngp*2 + ngl][half]
    const uint4* bptr = g_Bpack + (size_t)((ks * 4 + ngp * 2) * 64) + lane;
    uint4 nb0 = __ldg(bptr);         // ngl0 half0
    uint4 nb1 = __ldg(bptr + 32);    // ngl0 half1
    uint4 nb2 = __ldg(bptr + 64);    // ngl1 half0
    uint4 nb3 = __ldg(bptr + 96);    // ngl1 half1

    for (int ch = 0; ch < NCHUNK; ++ch) {
        const int k0 = (ch * 4 + ks) * 8;
        uint32_t a0[4], a1[4];
        a0[0] = __float_as_uint(s.ab.A[k0 + fc][m0 + fr]);
        a0[1] = __float_as_uint(s.ab.A[k0 + fc][m0 + fr + 8]);
        a0[2] = __float_as_uint(s.ab.A[k0 + fc + 4][m0 + fr]);
        a0[3] = __float_as_uint(s.ab.A[k0 + fc + 4][m0 + fr + 8]);
        a1[0] = __float_as_uint(s.ab.A[k0 + fc][m0 + 16 + fr]);
        a1[1] = __float_as_uint(s.ab.A[k0 + fc][m0 + 16 + fr + 8]);
        a1[2] = __float_as_uint(s.ab.A[k0 + fc + 4][m0 + 16 + fr]);
        a1[3] = __float_as_uint(s.ab.A[k0 + fc + 4][m0 + 16 + fr + 8]);

        uint4 cb0 = nb0, cb1 = nb1, cb2 = nb2, cb3 = nb3;
        if (ch + 1 < NCHUNK) {                // prefetch next chunk's B
            bptr += 1024;
            nb0 = __ldg(bptr);
            nb1 = __ldg(bptr + 32);
            nb2 = __ldg(bptr + 64);
            nb3 = __ldg(bptr + 96);
        }

        mma_tf32(acc[0][0], a0, cb0.x, cb0.y);
        mma_tf32(acc[0][1], a0, cb0.z, cb0.w);
        mma_tf32(acc[0][2], a0, cb1.x, cb1.y);
        mma_tf32(acc[0][3], a0, cb1.z, cb1.w);
        mma_tf32(acc[0][4], a0, cb2.x, cb2.y);
        mma_tf32(acc[0][5], a0, cb2.z, cb2.w);
        mma_tf32(acc[0][6], a0, cb3.x, cb3.y);
        mma_tf32(acc[0][7], a0, cb3.z, cb3.w);
        mma_tf32(acc[1][0], a1, cb0.x, cb0.y);
        mma_tf32(acc[1][1], a1, cb0.z, cb0.w);
        mma_tf32(acc[1][2], a1, cb1.x, cb1.y);
        mma_tf32(acc[1][3], a1, cb1.z, cb1.w);
        mma_tf32(acc[1][4], a1, cb2.x, cb2.y);
        mma_tf32(acc[1][5], a1, cb2.z, cb2.w);
        mma_tf32(acc[1][6], a1, cb3.x, cb3.y);
        mma_tf32(acc[1][7], a1, cb3.z, cb3.w);
    }

    // ---- store k-split partials (A region is dead now) ----
    __syncthreads();
    {
        float* Cp = &s.ab.Cpart[ks][0][0];
        #pragma unroll
        for (int mt2 = 0; mt2 < 2; ++mt2) {
            const int row = m0 + mt2 * 16 + fr;
            #pragma unroll
            for (int nn = 0; nn < 8; ++nn) {
                const int col = ngp * 64 + nn * 8 + 2 * fc;
                Cp[row * 132 + col]           = acc[mt2][nn][0];
                Cp[row * 132 + col + 1]       = acc[mt2][nn][1];
                Cp[(row + 8) * 132 + col]     = acc[mt2][nn][2];
                Cp[(row + 8) * 132 + col + 1] = acc[mt2][nn][3];
            }
        }
    }
    __syncthreads();

    // ---- merge partials + relu + max-pool over nodes ----
    if (tid < 256) {
        const int q = tid >> 7, h = tid & 127;
        float mx = -3.0e38f;
        #pragma unroll 4
        for (int j = 0; j < N_; ++j) {
            const int row = q * 32 + j;
            float v = s.ab.Cpart[0][row][h] + s.ab.Cpart[1][row][h]
                    + s.ab.Cpart[2][row][h] + s.ab.Cpart[3][row][h];
            mx = fmaxf(mx, v);
        }
        g_pooled[(size_t)(bg0 + q) * H_ + h] = fmaxf(mx, 0.0f);
    }
}

// ---------------------------------------------------------------------------
// Kernel C: heads (unchanged from passing R9 version).
// ---------------------------------------------------------------------------
struct SmemH {
    float P[32][H_];
    float W[H_][H_];
    float Z[32][132];
    int   cols[32];
};

__global__ __launch_bounds__(256, 2) void heads_kernel(
    const float* __restrict__ actions,
    const float* __restrict__ W1,
    const float* __restrict__ b1,
    const float* __restrict__ W2,
    const float* __restrict__ b2,
    float* __restrict__ qout)
{
    extern __shared__ char raw[];
    SmemH& s = *reinterpret_cast<SmemH*>(raw);
    const int tid = threadIdx.x;
    const int a   = blockIdx.x >> 6;
    const int b0  = (blockIdx.x & 63) * 32;

    {
        const float4* ps = reinterpret_cast<const float4*>(g_pooled + (size_t)b0 * H_);
        float4* pd = reinterpret_cast<float4*>(&s.P[0][0]);
        #pragma unroll
        for (int p = 0; p < 4; ++p) pd[tid + p * 256] = ps[tid + p * 256];
        const float4* ws = reinterpret_cast<const float4*>(W1 + (size_t)a * H_ * H_);
        float4* wd = reinterpret_cast<float4*>(&s.W[0][0]);
        #pragma unroll
        for (int p = 0; p < 16; ++p) wd[tid + p * 256] = ws[tid + p * 256];
    }
    if (tid < 32) {
        const float* ap = actions + ((size_t)a * B_ + b0 + tid) * NACT_;
        float best = ap[0]; int col = 0;
        #pragma unroll
        for (int k = 1; k < NACT_; ++k) {
            float v = ap[k];
            if (v > best) { best = v; col = k; }
        }
        s.cols[tid] = col;
    }
    __syncthreads();
    {
        const int bi = tid >> 5;
        const int hi = tid & 31;
        float4 bv = *reinterpret_cast<const float4*>(b1 + a * H_ + hi * 4);
        uint64_t zp[4][2];
        #pragma unroll
        for (int r = 0; r < 4; ++r) {
            zp[r][0] = pk2(bv.x, bv.y);
            zp[r][1] = pk2(bv.z, bv.w);
        }
        #pragma unroll 4
        for (int k = 0; k < H_; ++k) {
            float4 wv = *reinterpret_cast<const float4*>(&s.W[k][hi * 4]);
            uint64_t w01 = pk2(wv.x, wv.y);
            uint64_t w23 = pk2(wv.z, wv.w);
            #pragma unroll
            for (int r = 0; r < 4; ++r) {
                float pv = s.P[bi * 4 + r][k];
                uint64_t pv2 = pk2(pv, pv);
                zp[r][0] = fma2(pv2, w01, zp[r][0]);
                zp[r][1] = fma2(pv2, w23, zp[r][1]);
            }
        }
        #pragma unroll
        for (int r = 0; r < 4; ++r) {
            float z0, z1, z2, z3;
            upk2(zp[r][0], z0, z1);
            upk2(zp[r][1], z2, z3);
            z0 = (z0 > 0.f) ? z0 : 0.01f * z0;
            z1 = (z1 > 0.f) ? z1 : 0.01f * z1;
            z2 = (z2 > 0.f) ? z2 : 0.01f * z2;
            z3 = (z3 > 0.f) ? z3 : 0.01f * z3;
            float* zr = &s.Z[bi * 4 + r][hi * 4];
            zr[0] = z0; zr[1] = z1; zr[2] = z2; zr[3] = z3;
        }
    }
    __syncthreads();
    {
        const int b  = tid >> 3;
        const int qt = tid & 7;
        const int col = s.cols[b];
        const float* w2p = W2 + (size_t)a * H_ * NACT_ + col;
        float part = 0.f;
        #pragma unroll 8
        for (int i = 0; i < 16; ++i) {
            int h = i * 8 + qt;
            part = fmaf(s.Z[b][h], __ldg(w2p + h * NACT_), part);
        }
        part += __shfl_xor_sync(0xffffffffu, part, 1);
        part += __shfl_xor_sync(0xffffffffu, part, 2);
        part += __shfl_xor_sync(0xffffffffu, part, 4);
        if (qt == 0)
            qout[(size_t)a * B_ + b0 + b] = part + b2[a * NACT_ + col];
    }
}

// ---------------------------------------------------------------------------
extern "C" void kernel_launch(void* const* d_in, const int* in_sizes, int n_in,
                              void* d_out, int out_size) {
    const float* unary   = (const float*)d_in[0];
    const int*   binary  = (const int*)  d_in[1];
    const float* actions = (const float*)d_in[2];
    const float* We      = (const float*)d_in[3];
    const float* be      = (const float*)d_in[4];
    const float* Wrel    = (const float*)d_in[5];
    const float* Wroot   = (const float*)d_in[6];
    const float* brel    = (const float*)d_in[7];
    const float* W1      = (const float*)d_in[8];
    const float* b1      = (const float*)d_in[9];
    const float* W2      = (const float*)d_in[10];
    const float* b2      = (const float*)d_in[11];
    float* qout = (float*)d_out;

    cudaFuncSetAttribute(critic_main, cudaFuncAttributeMaxDynamicSharedMemorySize,
                         (int)sizeof(SmemM));
    cudaFuncSetAttribute(heads_kernel, cudaFuncAttributeMaxDynamicSharedMemorySize,
                         (int)sizeof(SmemH));

    precompute_wcat<<<KTOT, H_>>>(We, be, Wrel, Wroot, brel);
    repack_b<<<KK_, 256>>>();
    critic_main<<<B_ / 2, 512, sizeof(SmemM)>>>(unary, binary);
    heads_kernel<<<NA_ * 64, 256, sizeof(SmemH)>>>(actions, W1, b1, W2, b2, qout);
}